// round 10
// baseline (speedup 1.0000x reference)
#include <cuda_runtime.h>
#include <cuda_fp16.h>
#include <cstdint>
#include <cstddef>

constexpr int B  = 65536;
constexpr int T  = 30;
constexpr int MT = 128;          // samples per CTA
constexpr int THREADS = 1024;    // 32 warps: 4 (m) x 8 (n), warp tile 32x32

// ---------------- Kernel0 smem offsets (bytes) ----------------
constexpr int SM0_X     = 0;       // [128 rows][stride 112B]  K=48 combined x tile
constexpr int SM0_WIH   = 14336;   // [256 n][stride 112B]     combined Wih0 hi/lo + bias
constexpr int SM0_HH0   = 43008;   // h0 hi, ping  [128][128B] swz
constexpr int SM0_HH1   = 59392;   // h0 hi, pong
constexpr int SM0_HL0   = 75776;   // h0 lo, ping
constexpr int SM0_HL1   = 92160;   // h0 lo, pong
constexpr int SM0_WHH_H = 108544;  // [256][128B] swz
constexpr int SM0_WHH_L = 141312;
constexpr int SM0_TOTAL = 174080;

// ---------------- Kernel1 smem offsets ----------------
constexpr int SM1_XH    = 0;       // staged h0 hi [128][128B] swz
constexpr int SM1_XL    = 16384;
constexpr int SM1_H1H0  = 32768;   // h1 hi ping
constexpr int SM1_H1H1  = 49152;   // h1 hi pong
constexpr int SM1_H1L0  = 65536;   // h1 lo ping
constexpr int SM1_H1L1  = 81920;   // h1 lo pong
constexpr int SM1_WIH_H = 98304;   // [256][128B] swz
constexpr int SM1_WIH_L = 131072;
constexpr int SM1_WHH_H = 163840;
constexpr int SM1_WHH_L = 196608;
constexpr int SM1_BIAS  = 229376;  // 256 f32, indexed by reordered gate col
constexpr int SM1_TOTAL = 230400;

// scratch: layer0 h (hi/lo fp16), [t][sample][8 x 16B chunks], coalesced both ways
__device__ uint4 g_h0hi[(size_t)T * B * 8];
__device__ uint4 g_h0lo[(size_t)T * B * 8];

// ---------------- helpers ----------------
__device__ __forceinline__ uint32_t smem_u32(const void* p) {
    uint32_t a;
    asm("{ .reg .u64 t; cvta.to.shared.u64 t, %1; cvt.u32.u64 %0, t; }"
        : "=r"(a) : "l"(p));
    return a;
}
__device__ __forceinline__ float sigf(float x) {
    return __fdividef(1.f, 1.f + __expf(-x));
}
__device__ __forceinline__ float tanh_(float x) {
    return __fdividef(2.f, 1.f + __expf(-2.f * x)) - 1.f;
}
__device__ __forceinline__ uint32_t f2h2(float a, float b) {
    __half2 h = __floats2half2_rn(a, b);
    return *reinterpret_cast<uint32_t*>(&h);
}

__device__ __forceinline__ void ldsm4(uint32_t (&r)[4], uint32_t addr) {
    asm volatile("ldmatrix.sync.aligned.m8n8.x4.shared.b16 {%0,%1,%2,%3}, [%4];"
        : "=r"(r[0]), "=r"(r[1]), "=r"(r[2]), "=r"(r[3]) : "r"(addr));
}
__device__ __forceinline__ void mma_f16(float (&d)[4], const uint32_t (&a)[4],
                                        uint32_t b0, uint32_t b1) {
    asm volatile(
        "mma.sync.aligned.m16n8k16.row.col.f32.f16.f16.f32 "
        "{%0,%1,%2,%3},{%4,%5,%6,%7},{%8,%9},{%0,%1,%2,%3};"
        : "+f"(d[0]), "+f"(d[1]), "+f"(d[2]), "+f"(d[3])
        : "r"(a[0]), "r"(a[1]), "r"(a[2]), "r"(a[3]), "r"(b0), "r"(b1));
}

// Warp GEMM: A tile (MI*16 rows) x NB B tiles (32 n-cols each), acc[MI][4][4].
// KS k16-steps; strides in bytes; SW = XOR-16B-chunk swizzle for 128B-stride tiles.
template<int KS, int SA, int SB, bool SWA, bool SWB, int NB, int MI>
__device__ __forceinline__ void gemm_acc(uint32_t aBase, uint32_t bBase0, uint32_t bBase1,
                                         float (&acc)[MI][4][4],
                                         int mrow0, int ncol0, int lane)
{
    const int grp = lane >> 3, j = lane & 7;
    const int arow_off = ((grp & 1) << 3) + j;
    const int ach_off  = grp >> 1;
    const int brow_off = ((grp >> 1) << 3) + j;
    const int bch_off  = grp & 1;
#pragma unroll
    for (int kk = 0; kk < KS; kk++) {
        uint32_t a[MI][4];
#pragma unroll
        for (int mi = 0; mi < MI; mi++) {
            int row = mrow0 + mi * 16 + arow_off;
            int ch  = 2 * kk + ach_off;
            uint32_t ad = aBase + row * SA + ((SWA ? (ch ^ (row & 7)) : ch) << 4);
            ldsm4(a[mi], ad);
        }
#pragma unroll
        for (int b = 0; b < NB; b++) {
            uint32_t bb = (b == 0) ? bBase0 : bBase1;
#pragma unroll
            for (int ni = 0; ni < 2; ni++) {
                int row = ncol0 + ni * 16 + brow_off;
                int ch  = 2 * kk + bch_off;
                uint32_t bd = bb + row * SB + ((SWB ? (ch ^ (row & 7)) : ch) << 4);
                uint32_t bf[4];
                ldsm4(bf, bd);
#pragma unroll
                for (int mi = 0; mi < MI; mi++) {
                    mma_f16(acc[mi][2 * ni],     a[mi], bf[0], bf[1]);
                    mma_f16(acc[mi][2 * ni + 1], a[mi], bf[2], bf[3]);
                }
            }
        }
    }
}

// Gate epilogue: acc (pre-activations, cols = unit*4+type) -> cell update ->
// h written hi/lo fp16 into the DESTINATION (ping-pong) swizzled smem tiles.
// No barrier needed between GEMM and this: destination != GEMM source buffer.
template<bool HASBIAS, int MI>
__device__ __forceinline__ void epilogue(float (&acc)[MI][4][4], float (&cs)[MI][4],
                                         char* sm, int hhOff, int hlOff,
                                         const float* bias,
                                         int mrow0, int ncol0, int lane)
{
    const int  odd   = lane & 1;
    const int  rb    = mrow0 + (lane >> 2) + (odd ? 8 : 0);
    const int  ub    = (ncol0 >> 2) + ((lane & 3) >> 1);
#pragma unroll
    for (int mi = 0; mi < MI; mi++) {
#pragma unroll
        for (int nj = 0; nj < 4; nj++) {
            float c0 = acc[mi][nj][0], c1 = acc[mi][nj][1];
            float c2 = acc[mi][nj][2], c3 = acc[mi][nj][3];
            if (HASBIAS) {
                int n0 = ncol0 + nj * 8 + 2 * (lane & 3);
                float b0 = bias[n0], b1 = bias[n0 + 1];
                c0 += b0; c1 += b1; c2 += b0; c3 += b1;
            }
            // even lanes hold (i,f) cols; odd lanes hold (g,o) cols; rows {r, r+8}
            float A0, A1, A2, A3;
            if (!odd) { A0 = sigf(c0);  A1 = sigf(c1); A2 = sigf(c2);  A3 = sigf(c3); }
            else      { A0 = tanh_(c0); A1 = sigf(c1); A2 = tanh_(c2); A3 = sigf(c3); }
            // exchange: even keeps row r (needs g,o from odd); odd keeps row r+8 (needs i,f)
            float v0 = odd ? A0 : A2;
            float v1 = odd ? A1 : A3;
            float r0 = __shfl_xor_sync(0xffffffffu, v0, 1);
            float r1 = __shfl_xor_sync(0xffffffffu, v1, 1);
            float iv = odd ? r0 : A0;
            float fv = odd ? r1 : A1;
            float gv = odd ? A2 : r0;
            float ov = odd ? A3 : r1;
            float cc = fv * cs[mi][nj] + iv * gv;
            cs[mi][nj] = cc;
            float hv = ov * tanh_(cc);
            int row = rb + mi * 16;
            int u   = ub + 2 * nj;
            __half hh = __float2half_rn(hv);
            __half hl = __float2half_rn(hv - __half2float(hh));
            int ch = u >> 3;
            int ba = row * 128 + ((ch ^ (row & 7)) << 4) + ((2 * u) & 15);
            *(__half*)(sm + hhOff + ba) = hh;
            *(__half*)(sm + hlOff + ba) = hl;
        }
    }
}

// split helper for weight fills
__device__ __forceinline__ void split2(float v, __half& hi, __half& lo) {
    hi = __float2half_rn(v);
    lo = __float2half_rn(v - __half2float(hi));
}

// =====================================================================
// Kernel 0: x -> h0 (hi/lo) -> global scratch
// =====================================================================
__global__ void __launch_bounds__(THREADS, 1) k_layer0(
    const float* __restrict__ x,
    const float* __restrict__ Wih, const float* __restrict__ Whh,
    const float* __restrict__ bih, const float* __restrict__ bhh)
{
    extern __shared__ __align__(1024) char sm[];
    const uint32_t sb = smem_u32(sm);
    const int tid = threadIdx.x, wid = tid >> 5, lane = tid & 31;
    const int mrow0 = (wid & 3) * 32;
    const int ncol0 = (wid >> 2) * 32;
    const int blk = blockIdx.x;

    // zero both h buffer pairs + Wih combined tile
    for (int i = tid; i < 65536 / 16; i += THREADS)
        ((uint4*)(sm + SM0_HH0))[i] = make_uint4(0, 0, 0, 0);
    for (int i = tid; i < 28672 / 16; i += THREADS)
        ((uint4*)(sm + SM0_WIH))[i] = make_uint4(0, 0, 0, 0);
    __syncthreads();

    // Wih0 combined tile: cols 0-8 Whi, 9 bias_hi, 16-24 Wlo, 25 bias_lo, 32-40 Whi
    for (int idx = tid; idx < 256 * 9; idx += THREADS) {
        int g = idx / 9, i2 = idx - g * 9;
        int n = (g & 63) * 4 + (g >> 6);
        __half hi, lo; split2(Wih[idx], hi, lo);
        *(__half*)(sm + SM0_WIH + n * 112 + 2 * i2)        = hi;
        *(__half*)(sm + SM0_WIH + n * 112 + 2 * (16 + i2)) = lo;
        *(__half*)(sm + SM0_WIH + n * 112 + 2 * (32 + i2)) = hi;
    }
    for (int g = tid; g < 256; g += THREADS) {
        int n = (g & 63) * 4 + (g >> 6);
        __half hi, lo; split2(bih[g] + bhh[g], hi, lo);
        *(__half*)(sm + SM0_WIH + n * 112 + 18) = hi;   // col 9
        *(__half*)(sm + SM0_WIH + n * 112 + 50) = lo;   // col 25
    }
    // Whh0 hi/lo tiles (swizzled)
    for (int idx = tid; idx < 256 * 64; idx += THREADS) {
        int g = idx >> 6, k = idx & 63;
        int n = (g & 63) * 4 + (g >> 6);
        __half hi, lo; split2(Whh[idx], hi, lo);
        int ba = n * 128 + (((k >> 3) ^ (n & 7)) << 4) + ((2 * k) & 15);
        *(__half*)(sm + SM0_WHH_H + ba) = hi;
        *(__half*)(sm + SM0_WHH_L + ba) = lo;
    }
    __syncthreads();

    float cs[2][4];
#pragma unroll
    for (int a = 0; a < 2; a++)
#pragma unroll
        for (int b = 0; b < 4; b++) cs[a][b] = 0.f;

    // prefetch x for t=0
    float xv[9];
    if (tid < MT) {
        const float* xr = x + ((size_t)(blk * MT + tid) * T + 0) * 9;
#pragma unroll
        for (int i = 0; i < 9; i++) xv[i] = xr[i];
    }

    for (int t = 0; t < T; t++) {
        const int rdH = (t & 1) ? SM0_HH1 : SM0_HH0;
        const int rdL = (t & 1) ? SM0_HL1 : SM0_HL0;
        const int wrH = (t & 1) ? SM0_HH0 : SM0_HH1;
        const int wrL = (t & 1) ? SM0_HL0 : SM0_HL1;

        // store h_{t-1} -> global scratch (reads rd buffers: read/read vs GEMM)
        if (t > 0) {
            int row = tid >> 3, ch = tid & 7;
            uint32_t sa = row * 128 + ((ch ^ (row & 7)) << 4);
            size_t gi = ((size_t)(t - 1) * B + (size_t)blk * MT + row) * 8 + ch;
            g_h0hi[gi] = *(uint4*)(sm + rdH + sa);
            g_h0lo[gi] = *(uint4*)(sm + rdL + sa);
        }

        // stage x_t: K=48 combined tile (xhi|1|0.., xhi|1|0.., xlo|0..)
        if (tid < MT) {
            float vl[9];
#pragma unroll
            for (int i = 0; i < 9; i++) {
                __half h = __float2half_rn(xv[i]);
                vl[i] = xv[i] - __half2float(h);
            }
            char* rp = sm + SM0_X + tid * 112;
            uint4 c0 = make_uint4(f2h2(xv[0], xv[1]), f2h2(xv[2], xv[3]),
                                  f2h2(xv[4], xv[5]), f2h2(xv[6], xv[7]));
            uint4 c1 = make_uint4(f2h2(xv[8], 1.0f), 0, 0, 0);
            uint4 c4 = make_uint4(f2h2(vl[0], vl[1]), f2h2(vl[2], vl[3]),
                                  f2h2(vl[4], vl[5]), f2h2(vl[6], vl[7]));
            uint4 c5 = make_uint4(f2h2(vl[8], 0.f), 0, 0, 0);
            ((uint4*)rp)[0] = c0;  ((uint4*)rp)[1] = c1;
            ((uint4*)rp)[2] = c0;  ((uint4*)rp)[3] = c1;
            ((uint4*)rp)[4] = c4;  ((uint4*)rp)[5] = c5;
        }
        __syncthreads();

        // prefetch x for t+1 (overlaps with GEMM below)
        if (t + 1 < T && tid < MT) {
            const float* xr = x + ((size_t)(blk * MT + tid) * T + (t + 1)) * 9;
#pragma unroll
            for (int i = 0; i < 9; i++) xv[i] = xr[i];
        }

        float acc[2][4][4];
#pragma unroll
        for (int a = 0; a < 2; a++)
#pragma unroll
            for (int b = 0; b < 4; b++)
#pragma unroll
                for (int q = 0; q < 4; q++) acc[a][b][q] = 0.f;

        gemm_acc<3, 112, 112, false, false, 1, 2>(sb + SM0_X, sb + SM0_WIH, 0,
                                                  acc, mrow0, ncol0, lane);
        gemm_acc<4, 128, 128, true, true, 2, 2>(sb + rdH, sb + SM0_WHH_H,
                                                sb + SM0_WHH_L, acc, mrow0, ncol0, lane);
        gemm_acc<4, 128, 128, true, true, 1, 2>(sb + rdL, sb + SM0_WHH_H, 0,
                                                acc, mrow0, ncol0, lane);

        // NO sync: epilogue writes ping-pong destination, disjoint from rd buffers
        epilogue<false, 2>(acc, cs, sm, wrH, wrL, nullptr, mrow0, ncol0, lane);
        __syncthreads();
    }

    // store final h_{T-1} (lives in buf[T&1] = buf0)
    {
        const int rdH = (T & 1) ? SM0_HH1 : SM0_HH0;
        const int rdL = (T & 1) ? SM0_HL1 : SM0_HL0;
        int row = tid >> 3, ch = tid & 7;
        uint32_t sa = row * 128 + ((ch ^ (row & 7)) << 4);
        size_t gi = ((size_t)(T - 1) * B + (size_t)blk * MT + row) * 8 + ch;
        g_h0hi[gi] = *(uint4*)(sm + rdH + sa);
        g_h0lo[gi] = *(uint4*)(sm + rdL + sa);
    }
}

// =====================================================================
// Kernel 1: h0 -> LSTM -> LayerNorm(h_T) -> out
// =====================================================================
__global__ void __launch_bounds__(THREADS, 1) k_layer1(
    const float* __restrict__ Wih, const float* __restrict__ Whh,
    const float* __restrict__ bih, const float* __restrict__ bhh,
    const float* __restrict__ gamma, const float* __restrict__ beta,
    float* __restrict__ out)
{
    extern __shared__ __align__(1024) char sm[];
    const uint32_t sb = smem_u32(sm);
    const int tid = threadIdx.x, wid = tid >> 5, lane = tid & 31;
    const int mrow0 = (wid & 3) * 32;
    const int ncol0 = (wid >> 2) * 32;
    const int blk = blockIdx.x;

    // zero both h1 buffer pairs
    for (int i = tid; i < 65536 / 16; i += THREADS)
        ((uint4*)(sm + SM1_H1H0))[i] = make_uint4(0, 0, 0, 0);
    // weights (swizzled hi/lo) + bias table (reordered)
    for (int idx = tid; idx < 256 * 64; idx += THREADS) {
        int g = idx >> 6, k = idx & 63;
        int n = (g & 63) * 4 + (g >> 6);
        int ba = n * 128 + (((k >> 3) ^ (n & 7)) << 4) + ((2 * k) & 15);
        __half hi, lo;
        split2(Wih[idx], hi, lo);
        *(__half*)(sm + SM1_WIH_H + ba) = hi;
        *(__half*)(sm + SM1_WIH_L + ba) = lo;
        split2(Whh[idx], hi, lo);
        *(__half*)(sm + SM1_WHH_H + ba) = hi;
        *(__half*)(sm + SM1_WHH_L + ba) = lo;
    }
    for (int g = tid; g < 256; g += THREADS) {
        int n = (g & 63) * 4 + (g >> 6);
        ((float*)(sm + SM1_BIAS))[n] = bih[g] + bhh[g];
    }
    __syncthreads();

    float cs[2][4];
#pragma unroll
    for (int a = 0; a < 2; a++)
#pragma unroll
        for (int b = 0; b < 4; b++) cs[a][b] = 0.f;

    // prefetch h0 for t=0 (1024 threads cover 1024 hi + 1024 lo uint4s)
    uint4 ph, pl;
    {
        size_t base = ((size_t)0 * B + (size_t)blk * MT) * 8;
        ph = g_h0hi[base + tid];
        pl = g_h0lo[base + tid];
    }

    for (int t = 0; t < T; t++) {
        const int rdH = (t & 1) ? SM1_H1H1 : SM1_H1H0;
        const int rdL = (t & 1) ? SM1_H1L1 : SM1_H1L0;
        const int wrH = (t & 1) ? SM1_H1H0 : SM1_H1H1;
        const int wrL = (t & 1) ? SM1_H1L0 : SM1_H1L1;

        // stage h0_t from prefetched regs into swizzled X tiles
        {
            int row = tid >> 3, ch = tid & 7;
            uint32_t sa = row * 128 + ((ch ^ (row & 7)) << 4);
            *(uint4*)(sm + SM1_XH + sa) = ph;
            *(uint4*)(sm + SM1_XL + sa) = pl;
        }
        __syncthreads();

        // prefetch next timestep (overlaps with GEMM)
        if (t + 1 < T) {
            size_t base = ((size_t)(t + 1) * B + (size_t)blk * MT) * 8;
            ph = g_h0hi[base + tid];
            pl = g_h0lo[base + tid];
        }

        float acc[2][4][4];
#pragma unroll
        for (int a = 0; a < 2; a++)
#pragma unroll
            for (int b = 0; b < 4; b++)
#pragma unroll
                for (int q = 0; q < 4; q++) acc[a][b][q] = 0.f;

        gemm_acc<4, 128, 128, true, true, 2, 2>(sb + SM1_XH, sb + SM1_WIH_H,
                                                sb + SM1_WIH_L, acc, mrow0, ncol0, lane);
        gemm_acc<4, 128, 128, true, true, 1, 2>(sb + SM1_XL, sb + SM1_WIH_H, 0,
                                                acc, mrow0, ncol0, lane);
        gemm_acc<4, 128, 128, true, true, 2, 2>(sb + rdH, sb + SM1_WHH_H,
                                                sb + SM1_WHH_L, acc, mrow0, ncol0, lane);
        gemm_acc<4, 128, 128, true, true, 1, 2>(sb + rdL, sb + SM1_WHH_H, 0,
                                                acc, mrow0, ncol0, lane);

        // NO sync: epilogue writes ping-pong destination, disjoint from rd buffers
        epilogue<true, 2>(acc, cs, sm, wrH, wrL,
                          (const float*)(sm + SM1_BIAS), mrow0, ncol0, lane);
        __syncthreads();
    }

    // LayerNorm over final h1 (hi+lo reconstruct ~fp32), one thread per sample.
    // h_{T-1} lives in buf[T&1] = buf0.
    if (tid < MT) {
        const int rdH = (T & 1) ? SM1_H1H1 : SM1_H1H0;
        const int rdL = (T & 1) ? SM1_H1L1 : SM1_H1L0;
        int row = tid;
        float hv[64];
#pragma unroll
        for (int ch = 0; ch < 8; ch++) {
            uint32_t sa = row * 128 + ((ch ^ (row & 7)) << 4);
            uint4 vh = *(uint4*)(sm + rdH + sa);
            uint4 vl = *(uint4*)(sm + rdL + sa);
            const __half2* phh = (const __half2*)&vh;
            const __half2* pll = (const __half2*)&vl;
#pragma unroll
            for (int q = 0; q < 4; q++) {
                float2 a = __half22float2(phh[q]);
                float2 b2 = __half22float2(pll[q]);
                hv[ch * 8 + 2 * q]     = a.x + b2.x;
                hv[ch * 8 + 2 * q + 1] = a.y + b2.y;
            }
        }
        float s = 0.f;
#pragma unroll
        for (int k = 0; k < 64; k++) s += hv[k];
        float mean = s * (1.f / 64.f);
        float vs = 0.f;
#pragma unroll
        for (int k = 0; k < 64; k++) { float d = hv[k] - mean; vs += d * d; }
        float rstd = rsqrtf(vs * (1.f / 64.f) + 1e-5f);
        float4* op = (float4*)(out + (size_t)(blk * MT + row) * 64);
#pragma unroll
        for (int k = 0; k < 64; k += 4) {
            float4 o;
            o.x = (hv[k + 0] - mean) * rstd * gamma[k + 0] + beta[k + 0];
            o.y = (hv[k + 1] - mean) * rstd * gamma[k + 1] + beta[k + 1];
            o.z = (hv[k + 2] - mean) * rstd * gamma[k + 2] + beta[k + 2];
            o.w = (hv[k + 3] - mean) * rstd * gamma[k + 3] + beta[k + 3];
            op[k >> 2] = o;
        }
    }
}

// =====================================================================
extern "C" void kernel_launch(void* const* d_in, const int* in_sizes, int n_in,
                              void* d_out, int out_size) {
    (void)in_sizes; (void)n_in; (void)out_size;
    const float* x     = (const float*)d_in[0];
    const float* Wih0  = (const float*)d_in[1];
    const float* Whh0  = (const float*)d_in[2];
    const float* bih0  = (const float*)d_in[3];
    const float* bhh0  = (const float*)d_in[4];
    const float* Wih1  = (const float*)d_in[5];
    const float* Whh1  = (const float*)d_in[6];
    const float* bih1  = (const float*)d_in[7];
    const float* bhh1  = (const float*)d_in[8];
    const float* gamma = (const float*)d_in[9];
    const float* beta  = (const float*)d_in[10];
    float* out = (float*)d_out;

    cudaFuncSetAttribute(k_layer0, cudaFuncAttributeMaxDynamicSharedMemorySize, SM0_TOTAL);
    cudaFuncSetAttribute(k_layer1, cudaFuncAttributeMaxDynamicSharedMemorySize, SM1_TOTAL);

    k_layer0<<<B / MT, THREADS, SM0_TOTAL>>>(x, Wih0, Whh0, bih0, bhh0);
    k_layer1<<<B / MT, THREADS, SM1_TOTAL>>>(Wih1, Whh1, bih1, bhh1, gamma, beta, out);
}

// round 11
// speedup vs baseline: 2.3617x; 2.3617x over previous
#include <cuda_runtime.h>
#include <cuda_fp16.h>
#include <cstdint>
#include <cstddef>

constexpr int B  = 65536;
constexpr int T  = 30;
constexpr int MT = 128;          // samples per CTA
constexpr int THREADS = 512;     // 16 warps: 2 (m) x 8 (n), warp tile 64x32

// ---------------- Kernel0 smem offsets (bytes) ----------------
constexpr int SM0_X     = 0;       // [128 rows][stride 80B] K=32: (xhi|1) twice
constexpr int SM0_WIH   = 10240;   // [256 n][stride 80B] grp0=Whi+bias_hi, grp1=Wlo+bias_lo
constexpr int SM0_HH0   = 30720;   // h0 fp16 ping [128][128B] swz
constexpr int SM0_HH1   = 47104;   // h0 fp16 pong
constexpr int SM0_WHH_H = 63488;   // [256][128B] swz
constexpr int SM0_WHH_L = 96256;
constexpr int SM0_TOTAL = 129024;

// ---------------- Kernel1 smem offsets ----------------
constexpr int SM1_XH    = 0;       // staged h0 fp16 [128][128B] swz
constexpr int SM1_H1H0  = 16384;   // h1 fp16 ping
constexpr int SM1_H1H1  = 32768;   // h1 fp16 pong
constexpr int SM1_WIH_H = 49152;   // [256][128B] swz
constexpr int SM1_WIH_L = 81920;
constexpr int SM1_WHH_H = 114688;
constexpr int SM1_WHH_L = 147456;
constexpr int SM1_BIAS  = 180224;  // 256 f32, reordered gate cols
constexpr int SM1_LN    = 181248;  // [128][68] f32 final h for LayerNorm
constexpr int SM1_TOTAL = 181248 + 128 * 68 * 4;   // 216064

// scratch: layer0 h fp16, [t][sample][8 x 16B chunks], coalesced both ways
__device__ uint4 g_h0[(size_t)T * B * 8];

// ---------------- helpers ----------------
__device__ __forceinline__ uint32_t smem_u32(const void* p) {
    uint32_t a;
    asm("{ .reg .u64 t; cvta.to.shared.u64 t, %1; cvt.u32.u64 %0, t; }"
        : "=r"(a) : "l"(p));
    return a;
}
__device__ __forceinline__ float sigf(float x) {
    return __fdividef(1.f, 1.f + __expf(-x));
}
__device__ __forceinline__ float tanh_(float x) {
    return __fdividef(2.f, 1.f + __expf(-2.f * x)) - 1.f;
}
__device__ __forceinline__ uint32_t f2h2(float a, float b) {
    __half2 h = __floats2half2_rn(a, b);
    return *reinterpret_cast<uint32_t*>(&h);
}

__device__ __forceinline__ void ldsm4(uint32_t (&r)[4], uint32_t addr) {
    asm volatile("ldmatrix.sync.aligned.m8n8.x4.shared.b16 {%0,%1,%2,%3}, [%4];"
        : "=r"(r[0]), "=r"(r[1]), "=r"(r[2]), "=r"(r[3]) : "r"(addr));
}
__device__ __forceinline__ void mma_f16(float (&d)[4], const uint32_t (&a)[4],
                                        uint32_t b0, uint32_t b1) {
    asm volatile(
        "mma.sync.aligned.m16n8k16.row.col.f32.f16.f16.f32 "
        "{%0,%1,%2,%3},{%4,%5,%6,%7},{%8,%9},{%0,%1,%2,%3};"
        : "+f"(d[0]), "+f"(d[1]), "+f"(d[2]), "+f"(d[3])
        : "r"(a[0]), "r"(a[1]), "r"(a[2]), "r"(a[3]), "r"(b0), "r"(b1));
}

// Warp GEMM: A tile (MI*16 rows) x NB B tiles (32 n-cols each), acc[MI][4][4].
// KS k16-steps; strides in bytes; SW = XOR-16B-chunk swizzle for 128B-stride tiles.
template<int KS, int SA, int SB, bool SWA, bool SWB, int NB, int MI>
__device__ __forceinline__ void gemm_acc(uint32_t aBase, uint32_t bBase0, uint32_t bBase1,
                                         float (&acc)[MI][4][4],
                                         int mrow0, int ncol0, int lane)
{
    const int grp = lane >> 3, j = lane & 7;
    const int arow_off = ((grp & 1) << 3) + j;
    const int ach_off  = grp >> 1;
    const int brow_off = ((grp >> 1) << 3) + j;
    const int bch_off  = grp & 1;
#pragma unroll
    for (int kk = 0; kk < KS; kk++) {
        uint32_t a[MI][4];
#pragma unroll
        for (int mi = 0; mi < MI; mi++) {
            int row = mrow0 + mi * 16 + arow_off;
            int ch  = 2 * kk + ach_off;
            uint32_t ad = aBase + row * SA + ((SWA ? (ch ^ (row & 7)) : ch) << 4);
            ldsm4(a[mi], ad);
        }
#pragma unroll
        for (int b = 0; b < NB; b++) {
            uint32_t bb = (b == 0) ? bBase0 : bBase1;
#pragma unroll
            for (int ni = 0; ni < 2; ni++) {
                int row = ncol0 + ni * 16 + brow_off;
                int ch  = 2 * kk + bch_off;
                uint32_t bd = bb + row * SB + ((SWB ? (ch ^ (row & 7)) : ch) << 4);
                uint32_t bf[4];
                ldsm4(bf, bd);
#pragma unroll
                for (int mi = 0; mi < MI; mi++) {
                    mma_f16(acc[mi][2 * ni],     a[mi], bf[0], bf[1]);
                    mma_f16(acc[mi][2 * ni + 1], a[mi], bf[2], bf[3]);
                }
            }
        }
    }
}

// Gate epilogue: acc (pre-activations, cols = unit*4+type) -> cell update ->
// h written fp16 into DESTINATION ping-pong tile (disjoint from GEMM sources,
// so no barrier before it), or fp32 into the LN buffer on the last step.
template<bool HASBIAS, bool LNOUT, int MI>
__device__ __forceinline__ void epilogue(float (&acc)[MI][4][4], float (&cs)[MI][4],
                                         char* sm, int hhOff, const float* bias,
                                         int lnOff, int mrow0, int ncol0, int lane)
{
    const int  odd   = lane & 1;
    const int  rb    = mrow0 + (lane >> 2) + (odd ? 8 : 0);
    const int  ub    = (ncol0 >> 2) + ((lane & 3) >> 1);
#pragma unroll
    for (int mi = 0; mi < MI; mi++) {
#pragma unroll
        for (int nj = 0; nj < 4; nj++) {
            float c0 = acc[mi][nj][0], c1 = acc[mi][nj][1];
            float c2 = acc[mi][nj][2], c3 = acc[mi][nj][3];
            if (HASBIAS) {
                int n0 = ncol0 + nj * 8 + 2 * (lane & 3);
                float b0 = bias[n0], b1 = bias[n0 + 1];
                c0 += b0; c1 += b1; c2 += b0; c3 += b1;
            }
            // even lanes hold (i,f) cols; odd lanes hold (g,o) cols; rows {r, r+8}
            float A0, A1, A2, A3;
            if (!odd) { A0 = sigf(c0);  A1 = sigf(c1); A2 = sigf(c2);  A3 = sigf(c3); }
            else      { A0 = tanh_(c0); A1 = sigf(c1); A2 = tanh_(c2); A3 = sigf(c3); }
            // exchange: even keeps row r (needs g,o from odd); odd keeps row r+8 (needs i,f)
            float v0 = odd ? A0 : A2;
            float v1 = odd ? A1 : A3;
            float r0 = __shfl_xor_sync(0xffffffffu, v0, 1);
            float r1 = __shfl_xor_sync(0xffffffffu, v1, 1);
            float iv = odd ? r0 : A0;
            float fv = odd ? r1 : A1;
            float gv = odd ? A2 : r0;
            float ov = odd ? A3 : r1;
            float cc = fv * cs[mi][nj] + iv * gv;
            cs[mi][nj] = cc;
            float hv = ov * tanh_(cc);
            int row = rb + mi * 16;
            int u   = ub + 2 * nj;
            if (LNOUT) {
                ((float*)(sm + lnOff))[row * 68 + u] = hv;
            } else {
                __half hh = __float2half_rn(hv);
                int ch = u >> 3;
                int ba = row * 128 + ((ch ^ (row & 7)) << 4) + ((2 * u) & 15);
                *(__half*)(sm + hhOff + ba) = hh;
            }
        }
    }
}

// split helper for weight fills
__device__ __forceinline__ void split2(float v, __half& hi, __half& lo) {
    hi = __float2half_rn(v);
    lo = __float2half_rn(v - __half2float(hi));
}

// =====================================================================
// Kernel 0: x -> h0 (fp16) -> global scratch
// =====================================================================
__global__ void __launch_bounds__(THREADS, 1) k_layer0(
    const float* __restrict__ x,
    const float* __restrict__ Wih, const float* __restrict__ Whh,
    const float* __restrict__ bih, const float* __restrict__ bhh)
{
    extern __shared__ __align__(1024) char sm[];
    const uint32_t sb = smem_u32(sm);
    const int tid = threadIdx.x, wid = tid >> 5, lane = tid & 31;
    const int mrow0 = (wid & 1) * 64;
    const int ncol0 = (wid >> 1) * 32;
    const int blk = blockIdx.x;

    // zero h ping-pong + X + WIH regions
    for (int i = tid; i < 32768 / 16; i += THREADS)
        ((uint4*)(sm + SM0_HH0))[i] = make_uint4(0, 0, 0, 0);
    for (int i = tid; i < 30720 / 16; i += THREADS)
        ((uint4*)(sm + SM0_X))[i] = make_uint4(0, 0, 0, 0);
    __syncthreads();

    // Wih0 tile [256][80B]: grp0 (bytes 0-31) = Whi cols0-8 + bias_hi col9;
    //                       grp1 (bytes 32-63) = Wlo + bias_lo
    for (int idx = tid; idx < 256 * 9; idx += THREADS) {
        int g = idx / 9, i2 = idx - g * 9;
        int n = (g & 63) * 4 + (g >> 6);
        __half hi, lo; split2(Wih[idx], hi, lo);
        *(__half*)(sm + SM0_WIH + n * 80 + 2 * i2)      = hi;
        *(__half*)(sm + SM0_WIH + n * 80 + 32 + 2 * i2) = lo;
    }
    for (int g = tid; g < 256; g += THREADS) {
        int n = (g & 63) * 4 + (g >> 6);
        __half hi, lo; split2(bih[g] + bhh[g], hi, lo);
        *(__half*)(sm + SM0_WIH + n * 80 + 18)      = hi;   // col 9 grp0
        *(__half*)(sm + SM0_WIH + n * 80 + 32 + 18) = lo;   // col 9 grp1
    }
    // Whh0 hi/lo tiles (swizzled)
    for (int idx = tid; idx < 256 * 64; idx += THREADS) {
        int g = idx >> 6, k = idx & 63;
        int n = (g & 63) * 4 + (g >> 6);
        __half hi, lo; split2(Whh[idx], hi, lo);
        int ba = n * 128 + (((k >> 3) ^ (n & 7)) << 4) + ((2 * k) & 15);
        *(__half*)(sm + SM0_WHH_H + ba) = hi;
        *(__half*)(sm + SM0_WHH_L + ba) = lo;
    }
    __syncthreads();

    float cs[4][4];
#pragma unroll
    for (int a = 0; a < 4; a++)
#pragma unroll
        for (int b = 0; b < 4; b++) cs[a][b] = 0.f;

    // prefetch x for t=0
    float xv[9];
    if (tid < MT) {
        const float* xr = x + ((size_t)(blk * MT + tid) * T + 0) * 9;
#pragma unroll
        for (int i = 0; i < 9; i++) xv[i] = xr[i];
    }

    for (int t = 0; t < T; t++) {
        const int rdH = (t & 1) ? SM0_HH1 : SM0_HH0;
        const int wrH = (t & 1) ? SM0_HH0 : SM0_HH1;

        // store h_{t-1} -> global scratch (reads rd: read/read vs H-GEMM)
        if (t > 0) {
            for (int i = tid; i < 1024; i += THREADS) {
                int row = i >> 3, ch = i & 7;
                uint32_t sa = row * 128 + ((ch ^ (row & 7)) << 4);
                size_t gi = ((size_t)(t - 1) * B + (size_t)blk * MT + row) * 8 + ch;
                g_h0[gi] = *(uint4*)(sm + SM0_X);   // placeholder replaced below
                g_h0[gi] = *(uint4*)(sm + rdH + sa);
            }
        }

        // stage x_t into K=32 tile: grp0 = xhi|1.0, grp1 = xhi|1.0 (pairs Whi then Wlo)
        if (tid < MT) {
            char* rp = sm + SM0_X + tid * 80;
            uint4 c0 = make_uint4(f2h2(xv[0], xv[1]), f2h2(xv[2], xv[3]),
                                  f2h2(xv[4], xv[5]), f2h2(xv[6], xv[7]));
            uint4 c1 = make_uint4(f2h2(xv[8], 1.0f), 0, 0, 0);
            ((uint4*)rp)[0] = c0;  ((uint4*)rp)[1] = c1;
            ((uint4*)rp)[2] = c0;  ((uint4*)rp)[3] = c1;
        }

        float acc[4][4][4];
#pragma unroll
        for (int a = 0; a < 4; a++)
#pragma unroll
            for (int b = 0; b < 4; b++)
#pragma unroll
                for (int q = 0; q < 4; q++) acc[a][b][q] = 0.f;

        // H-GEMM first (depends only on prev epilogue + trailing sync)
        gemm_acc<4, 128, 128, true, true, 2, 4>(sb + rdH, sb + SM0_WHH_H,
                                                sb + SM0_WHH_L, acc, mrow0, ncol0, lane);
        __syncthreads();   // drains x stores (hidden behind H-GEMM)

        // prefetch x for t+1 (overlaps X-GEMM + epilogue)
        if (t + 1 < T && tid < MT) {
            const float* xr = x + ((size_t)(blk * MT + tid) * T + (t + 1)) * 9;
#pragma unroll
            for (int i = 0; i < 9; i++) xv[i] = xr[i];
        }

        gemm_acc<2, 80, 80, false, false, 1, 4>(sb + SM0_X, sb + SM0_WIH, 0,
                                                acc, mrow0, ncol0, lane);

        // epilogue writes wr tile (disjoint from rd/X) — no barrier before it
        epilogue<false, false, 4>(acc, cs, sm, wrH, nullptr, 0, mrow0, ncol0, lane);
        __syncthreads();
    }

    // store final h_{T-1} (lives in buf[T&1] = buf0)
    {
        const int rdH = (T & 1) ? SM0_HH1 : SM0_HH0;
        for (int i = tid; i < 1024; i += THREADS) {
            int row = i >> 3, ch = i & 7;
            uint32_t sa = row * 128 + ((ch ^ (row & 7)) << 4);
            size_t gi = ((size_t)(T - 1) * B + (size_t)blk * MT + row) * 8 + ch;
            g_h0[gi] = *(uint4*)(sm + rdH + sa);
        }
    }
}

// =====================================================================
// Kernel 1: h0 -> LSTM -> LayerNorm(h_T) -> out
// =====================================================================
__global__ void __launch_bounds__(THREADS, 1) k_layer1(
    const float* __restrict__ Wih, const float* __restrict__ Whh,
    const float* __restrict__ bih, const float* __restrict__ bhh,
    const float* __restrict__ gamma, const float* __restrict__ beta,
    float* __restrict__ out)
{
    extern __shared__ __align__(1024) char sm[];
    const uint32_t sb = smem_u32(sm);
    const int tid = threadIdx.x, wid = tid >> 5, lane = tid & 31;
    const int mrow0 = (wid & 1) * 64;
    const int ncol0 = (wid >> 1) * 32;
    const int blk = blockIdx.x;

    // zero h1 ping-pong
    for (int i = tid; i < 32768 / 16; i += THREADS)
        ((uint4*)(sm + SM1_H1H0))[i] = make_uint4(0, 0, 0, 0);
    // weights (swizzled hi/lo) + bias table (reordered)
    for (int idx = tid; idx < 256 * 64; idx += THREADS) {
        int g = idx >> 6, k = idx & 63;
        int n = (g & 63) * 4 + (g >> 6);
        int ba = n * 128 + (((k >> 3) ^ (n & 7)) << 4) + ((2 * k) & 15);
        __half hi, lo;
        split2(Wih[idx], hi, lo);
        *(__half*)(sm + SM1_WIH_H + ba) = hi;
        *(__half*)(sm + SM1_WIH_L + ba) = lo;
        split2(Whh[idx], hi, lo);
        *(__half*)(sm + SM1_WHH_H + ba) = hi;
        *(__half*)(sm + SM1_WHH_L + ba) = lo;
    }
    for (int g = tid; g < 256; g += THREADS) {
        int n = (g & 63) * 4 + (g >> 6);
        ((float*)(sm + SM1_BIAS))[n] = bih[g] + bhh[g];
    }
    __syncthreads();

    float cs[4][4];
#pragma unroll
    for (int a = 0; a < 4; a++)
#pragma unroll
        for (int b = 0; b < 4; b++) cs[a][b] = 0.f;

    // prefetch h0 for t=0 (1024 uint4, 2 per thread; layout linear in i)
    uint4 ph[2];
    {
        size_t base = ((size_t)0 * B + (size_t)blk * MT) * 8;
#pragma unroll
        for (int r = 0; r < 2; r++) ph[r] = g_h0[base + tid + r * THREADS];
    }

    for (int t = 0; t < T; t++) {
        const int rdH = (t & 1) ? SM1_H1H1 : SM1_H1H0;
        const int wrH = (t & 1) ? SM1_H1H0 : SM1_H1H1;

        // stage h0_t from prefetched regs into swizzled X tile (STS only)
#pragma unroll
        for (int r = 0; r < 2; r++) {
            int i = tid + r * THREADS;
            int row = i >> 3, ch = i & 7;
            uint32_t sa = row * 128 + ((ch ^ (row & 7)) << 4);
            *(uint4*)(sm + SM1_XH + sa) = ph[r];
        }

        float acc[4][4][4];
#pragma unroll
        for (int a = 0; a < 4; a++)
#pragma unroll
            for (int b = 0; b < 4; b++)
#pragma unroll
                for (int q = 0; q < 4; q++) acc[a][b][q] = 0.f;

        // H-GEMM first (h from prev epilogue; trailing sync of t-1 covers it)
        gemm_acc<4, 128, 128, true, true, 2, 4>(sb + rdH, sb + SM1_WHH_H,
                                                sb + SM1_WHH_L, acc, mrow0, ncol0, lane);
        __syncthreads();   // drains X stores (hidden behind H-GEMM)

        // prefetch next timestep (overlaps X-GEMM + epilogue)
        if (t + 1 < T) {
            size_t base = ((size_t)(t + 1) * B + (size_t)blk * MT) * 8;
#pragma unroll
            for (int r = 0; r < 2; r++) ph[r] = g_h0[base + tid + r * THREADS];
        }

        gemm_acc<4, 128, 128, true, true, 2, 4>(sb + SM1_XH, sb + SM1_WIH_H,
                                                sb + SM1_WIH_L, acc, mrow0, ncol0, lane);

        if (t < T - 1) {
            epilogue<true, false, 4>(acc, cs, sm, wrH,
                                     (const float*)(sm + SM1_BIAS), 0,
                                     mrow0, ncol0, lane);
        } else {
            // last step: write fp32 h into LN buffer (full precision for LayerNorm)
            epilogue<true, true, 4>(acc, cs, sm, 0,
                                    (const float*)(sm + SM1_BIAS), SM1_LN,
                                    mrow0, ncol0, lane);
        }
        __syncthreads();
    }

    // LayerNorm over final h1 (fp32 buffer), one thread per sample
    if (tid < MT) {
        const float* row = (const float*)(sm + SM1_LN) + tid * 68;
        float s = 0.f;
#pragma unroll
        for (int k = 0; k < 64; k++) s += row[k];
        float mean = s * (1.f / 64.f);
        float vs = 0.f;
#pragma unroll
        for (int k = 0; k < 64; k++) { float d = row[k] - mean; vs += d * d; }
        float rstd = rsqrtf(vs * (1.f / 64.f) + 1e-5f);
        float4* op = (float4*)(out + (size_t)(blk * MT + tid) * 64);
#pragma unroll
        for (int k = 0; k < 64; k += 4) {
            float4 o;
            o.x = (row[k + 0] - mean) * rstd * gamma[k + 0] + beta[k + 0];
            o.y = (row[k + 1] - mean) * rstd * gamma[k + 1] + beta[k + 1];
            o.z = (row[k + 2] - mean) * rstd * gamma[k + 2] + beta[k + 2];
            o.w = (row[k + 3] - mean) * rstd * gamma[k + 3] + beta[k + 3];
            op[k >> 2] = o;
        }
    }
}

// =====================================================================
extern "C" void kernel_launch(void* const* d_in, const int* in_sizes, int n_in,
                              void* d_out, int out_size) {
    (void)in_sizes; (void)n_in; (void)out_size;
    const float* x     = (const float*)d_in[0];
    const float* Wih0  = (const float*)d_in[1];
    const float* Whh0  = (const float*)d_in[2];
    const float* bih0  = (const float*)d_in[3];
    const float* bhh0  = (const float*)d_in[4];
    const float* Wih1  = (const float*)d_in[5];
    const float* Whh1  = (const float*)d_in[6];
    const float* bih1  = (const float*)d_in[7];
    const float* bhh1  = (const float*)d_in[8];
    const float* gamma = (const float*)d_in[9];
    const float* beta  = (const float*)d_in[10];
    float* out = (float*)d_out;

    cudaFuncSetAttribute(k_layer0, cudaFuncAttributeMaxDynamicSharedMemorySize, SM0_TOTAL);
    cudaFuncSetAttribute(k_layer1, cudaFuncAttributeMaxDynamicSharedMemorySize, SM1_TOTAL);

    k_layer0<<<B / MT, THREADS, SM0_TOTAL>>>(x, Wih0, Whh0, bih0, bhh0);
    k_layer1<<<B / MT, THREADS, SM1_TOTAL>>>(Wih1, Whh1, bih1, bhh1, gamma, beta, out);
}

// round 12
// speedup vs baseline: 2.8004x; 1.1858x over previous
#include <cuda_runtime.h>
#include <cuda_fp16.h>
#include <cstdint>
#include <cstddef>

constexpr int B  = 65536;
constexpr int T  = 30;
constexpr int MT = 128;          // samples per CTA
constexpr int THREADS = 512;     // 16 warps: 2 (m) x 8 (n), warp tile 64x32

// ---------------- Kernel0 smem offsets (bytes) ----------------
constexpr int SM0_X     = 0;       // [128 rows][stride 48B] K=16 x tile (cols0-8, rest 0)
constexpr int SM0_WIH   = 6144;    // [256 n][stride 48B] Whi fp16 (cols0-8, rest 0)
constexpr int SM0_BIAS  = 18432;   // 256 f32, reordered gate cols
constexpr int SM0_HH0   = 19456;   // h0 fp16 ping [128][128B] swz
constexpr int SM0_HH1   = 35840;   // h0 fp16 pong
constexpr int SM0_WHH_H = 52224;   // [256][128B] swz
constexpr int SM0_TOTAL = 84992;

// ---------------- Kernel1 smem offsets ----------------
constexpr int SM1_XH    = 0;       // staged h0 fp16 [128][128B] swz
constexpr int SM1_H1H0  = 16384;   // h1 fp16 ping
constexpr int SM1_H1H1  = 32768;   // h1 fp16 pong
constexpr int SM1_WIH_H = 49152;   // [256][128B] swz
constexpr int SM1_WHH_H = 81920;
constexpr int SM1_BIAS  = 114688;  // 256 f32, reordered gate cols
constexpr int SM1_LN    = 115712;  // [128][68] f32 final h for LayerNorm
constexpr int SM1_TOTAL = 115712 + 128 * 68 * 4;   // 150528

// scratch: layer0 h fp16, [t][sample][8 x 16B chunks], coalesced both ways
__device__ uint4 g_h0[(size_t)T * B * 8];

// ---------------- helpers ----------------
__device__ __forceinline__ uint32_t smem_u32(const void* p) {
    uint32_t a;
    asm("{ .reg .u64 t; cvta.to.shared.u64 t, %1; cvt.u32.u64 %0, t; }"
        : "=r"(a) : "l"(p));
    return a;
}
__device__ __forceinline__ float sigf(float x) {
    return __fdividef(1.f, 1.f + __expf(-x));
}
__device__ __forceinline__ float tanh_(float x) {
    return __fdividef(2.f, 1.f + __expf(-2.f * x)) - 1.f;
}
__device__ __forceinline__ uint32_t f2h2(float a, float b) {
    __half2 h = __floats2half2_rn(a, b);
    return *reinterpret_cast<uint32_t*>(&h);
}

__device__ __forceinline__ void ldsm4(uint32_t (&r)[4], uint32_t addr) {
    asm volatile("ldmatrix.sync.aligned.m8n8.x4.shared.b16 {%0,%1,%2,%3}, [%4];"
        : "=r"(r[0]), "=r"(r[1]), "=r"(r[2]), "=r"(r[3]) : "r"(addr));
}
__device__ __forceinline__ void mma_f16(float (&d)[4], const uint32_t (&a)[4],
                                        uint32_t b0, uint32_t b1) {
    asm volatile(
        "mma.sync.aligned.m16n8k16.row.col.f32.f16.f16.f32 "
        "{%0,%1,%2,%3},{%4,%5,%6,%7},{%8,%9},{%0,%1,%2,%3};"
        : "+f"(d[0]), "+f"(d[1]), "+f"(d[2]), "+f"(d[3])
        : "r"(a[0]), "r"(a[1]), "r"(a[2]), "r"(a[3]), "r"(b0), "r"(b1));
}

// Warp GEMM: A tile (MI*16 rows) x one B tile (32 n-cols), acc[MI][4][4].
// KS k16-steps; strides in bytes; SW = XOR-16B-chunk swizzle for 128B-stride tiles.
template<int KS, int SA, int SB, bool SWA, bool SWB, int MI>
__device__ __forceinline__ void gemm_acc(uint32_t aBase, uint32_t bBase,
                                         float (&acc)[MI][4][4],
                                         int mrow0, int ncol0, int lane)
{
    const int grp = lane >> 3, j = lane & 7;
    const int arow_off = ((grp & 1) << 3) + j;
    const int ach_off  = grp >> 1;
    const int brow_off = ((grp >> 1) << 3) + j;
    const int bch_off  = grp & 1;
#pragma unroll
    for (int kk = 0; kk < KS; kk++) {
        uint32_t a[MI][4];
#pragma unroll
        for (int mi = 0; mi < MI; mi++) {
            int row = mrow0 + mi * 16 + arow_off;
            int ch  = 2 * kk + ach_off;
            uint32_t ad = aBase + row * SA + ((SWA ? (ch ^ (row & 7)) : ch) << 4);
            ldsm4(a[mi], ad);
        }
#pragma unroll
        for (int ni = 0; ni < 2; ni++) {
            int row = ncol0 + ni * 16 + brow_off;
            int ch  = 2 * kk + bch_off;
            uint32_t bd = bBase + row * SB + ((SWB ? (ch ^ (row & 7)) : ch) << 4);
            uint32_t bf[4];
            ldsm4(bf, bd);
#pragma unroll
            for (int mi = 0; mi < MI; mi++) {
                mma_f16(acc[mi][2 * ni],     a[mi], bf[0], bf[1]);
                mma_f16(acc[mi][2 * ni + 1], a[mi], bf[2], bf[3]);
            }
        }
    }
}

// Gate epilogue: acc (pre-activations, cols = unit*4+type) + fp32 bias ->
// cell update -> h written fp16 into DESTINATION ping-pong tile (disjoint from
// GEMM sources, so no barrier before it), or fp32 into LN buffer on last step.
template<bool LNOUT, int MI>
__device__ __forceinline__ void epilogue(float (&acc)[MI][4][4], float (&cs)[MI][4],
                                         char* sm, int hhOff, const float* bias,
                                         int lnOff, int mrow0, int ncol0, int lane)
{
    const int  odd   = lane & 1;
    const int  rb    = mrow0 + (lane >> 2) + (odd ? 8 : 0);
    const int  ub    = (ncol0 >> 2) + ((lane & 3) >> 1);
#pragma unroll
    for (int mi = 0; mi < MI; mi++) {
#pragma unroll
        for (int nj = 0; nj < 4; nj++) {
            int n0 = ncol0 + nj * 8 + 2 * (lane & 3);
            float b0 = bias[n0], b1 = bias[n0 + 1];
            float c0 = acc[mi][nj][0] + b0, c1 = acc[mi][nj][1] + b1;
            float c2 = acc[mi][nj][2] + b0, c3 = acc[mi][nj][3] + b1;
            // even lanes hold (i,f) cols; odd lanes hold (g,o) cols; rows {r, r+8}
            float A0, A1, A2, A3;
            if (!odd) { A0 = sigf(c0);  A1 = sigf(c1); A2 = sigf(c2);  A3 = sigf(c3); }
            else      { A0 = tanh_(c0); A1 = sigf(c1); A2 = tanh_(c2); A3 = sigf(c3); }
            // exchange: even keeps row r (needs g,o from odd); odd keeps row r+8 (needs i,f)
            float v0 = odd ? A0 : A2;
            float v1 = odd ? A1 : A3;
            float r0 = __shfl_xor_sync(0xffffffffu, v0, 1);
            float r1 = __shfl_xor_sync(0xffffffffu, v1, 1);
            float iv = odd ? r0 : A0;
            float fv = odd ? r1 : A1;
            float gv = odd ? A2 : r0;
            float ov = odd ? A3 : r1;
            float cc = fv * cs[mi][nj] + iv * gv;
            cs[mi][nj] = cc;
            float hv = ov * tanh_(cc);
            int row = rb + mi * 16;
            int u   = ub + 2 * nj;
            if (LNOUT) {
                ((float*)(sm + lnOff))[row * 68 + u] = hv;
            } else {
                __half hh = __float2half_rn(hv);
                int ch = u >> 3;
                int ba = row * 128 + ((ch ^ (row & 7)) << 4) + ((2 * u) & 15);
                *(__half*)(sm + hhOff + ba) = hh;
            }
        }
    }
}

// =====================================================================
// Kernel 0: x -> h0 (fp16) -> global scratch
// =====================================================================
__global__ void __launch_bounds__(THREADS, 1) k_layer0(
    const float* __restrict__ x,
    const float* __restrict__ Wih, const float* __restrict__ Whh,
    const float* __restrict__ bih, const float* __restrict__ bhh)
{
    extern __shared__ __align__(1024) char sm[];
    const uint32_t sb = smem_u32(sm);
    const int tid = threadIdx.x, wid = tid >> 5, lane = tid & 31;
    const int mrow0 = (wid & 1) * 64;
    const int ncol0 = (wid >> 1) * 32;
    const int blk = blockIdx.x;

    // zero h ping-pong + X + WIH regions
    for (int i = tid; i < 32768 / 16; i += THREADS)
        ((uint4*)(sm + SM0_HH0))[i] = make_uint4(0, 0, 0, 0);
    for (int i = tid; i < 18432 / 16; i += THREADS)
        ((uint4*)(sm + SM0_X))[i] = make_uint4(0, 0, 0, 0);
    __syncthreads();

    // Wih0 fp16 [256 n][48B]: cols 0-8 weights, rest zero; bias fp32 table
    for (int idx = tid; idx < 256 * 9; idx += THREADS) {
        int g = idx / 9, i2 = idx - g * 9;
        int n = (g & 63) * 4 + (g >> 6);
        *(__half*)(sm + SM0_WIH + n * 48 + 2 * i2) = __float2half_rn(Wih[idx]);
    }
    for (int g = tid; g < 256; g += THREADS) {
        int n = (g & 63) * 4 + (g >> 6);
        ((float*)(sm + SM0_BIAS))[n] = bih[g] + bhh[g];
    }
    // Whh0 fp16 tile (swizzled)
    for (int idx = tid; idx < 256 * 64; idx += THREADS) {
        int g = idx >> 6, k = idx & 63;
        int n = (g & 63) * 4 + (g >> 6);
        int ba = n * 128 + (((k >> 3) ^ (n & 7)) << 4) + ((2 * k) & 15);
        *(__half*)(sm + SM0_WHH_H + ba) = __float2half_rn(Whh[idx]);
    }
    __syncthreads();

    float cs[4][4];
#pragma unroll
    for (int a = 0; a < 4; a++)
#pragma unroll
        for (int b = 0; b < 4; b++) cs[a][b] = 0.f;

    // prefetch x for t=0
    float xv[9];
    if (tid < MT) {
        const float* xr = x + ((size_t)(blk * MT + tid) * T + 0) * 9;
#pragma unroll
        for (int i = 0; i < 9; i++) xv[i] = xr[i];
    }

    for (int t = 0; t < T; t++) {
        const int rdH = (t & 1) ? SM0_HH1 : SM0_HH0;
        const int wrH = (t & 1) ? SM0_HH0 : SM0_HH1;

        // store h_{t-1} -> global scratch (reads rd: read/read vs H-GEMM)
        if (t > 0) {
            for (int i = tid; i < 1024; i += THREADS) {
                int row = i >> 3, ch = i & 7;
                uint32_t sa = row * 128 + ((ch ^ (row & 7)) << 4);
                size_t gi = ((size_t)(t - 1) * B + (size_t)blk * MT + row) * 8 + ch;
                g_h0[gi] = *(uint4*)(sm + rdH + sa);
            }
        }

        // stage x_t into K=16 tile (chunks 0-1; chunk 2 never read)
        if (tid < MT) {
            char* rp = sm + SM0_X + tid * 48;
            ((uint4*)rp)[0] = make_uint4(f2h2(xv[0], xv[1]), f2h2(xv[2], xv[3]),
                                         f2h2(xv[4], xv[5]), f2h2(xv[6], xv[7]));
            ((uint4*)rp)[1] = make_uint4(f2h2(xv[8], 0.f), 0, 0, 0);
        }

        float acc[4][4][4];
#pragma unroll
        for (int a = 0; a < 4; a++)
#pragma unroll
            for (int b = 0; b < 4; b++)
#pragma unroll
                for (int q = 0; q < 4; q++) acc[a][b][q] = 0.f;

        // H-GEMM first (depends only on prev epilogue + trailing sync)
        gemm_acc<4, 128, 128, true, true, 4>(sb + rdH, sb + SM0_WHH_H,
                                             acc, mrow0, ncol0, lane);
        __syncthreads();   // drains x stores (hidden behind H-GEMM)

        // prefetch x for t+1 (overlaps X-GEMM + epilogue)
        if (t + 1 < T && tid < MT) {
            const float* xr = x + ((size_t)(blk * MT + tid) * T + (t + 1)) * 9;
#pragma unroll
            for (int i = 0; i < 9; i++) xv[i] = xr[i];
        }

        gemm_acc<1, 48, 48, false, false, 4>(sb + SM0_X, sb + SM0_WIH,
                                             acc, mrow0, ncol0, lane);

        // epilogue writes wr tile (disjoint from rd/X) — no barrier before it
        epilogue<false, 4>(acc, cs, sm, wrH, (const float*)(sm + SM0_BIAS),
                           0, mrow0, ncol0, lane);
        __syncthreads();
    }

    // store final h_{T-1} (lives in buf[T&1] = buf0)
    {
        const int rdH = (T & 1) ? SM0_HH1 : SM0_HH0;
        for (int i = tid; i < 1024; i += THREADS) {
            int row = i >> 3, ch = i & 7;
            uint32_t sa = row * 128 + ((ch ^ (row & 7)) << 4);
            size_t gi = ((size_t)(T - 1) * B + (size_t)blk * MT + row) * 8 + ch;
            g_h0[gi] = *(uint4*)(sm + rdH + sa);
        }
    }
}

// =====================================================================
// Kernel 1: h0 -> LSTM -> LayerNorm(h_T) -> out
// =====================================================================
__global__ void __launch_bounds__(THREADS, 1) k_layer1(
    const float* __restrict__ Wih, const float* __restrict__ Whh,
    const float* __restrict__ bih, const float* __restrict__ bhh,
    const float* __restrict__ gamma, const float* __restrict__ beta,
    float* __restrict__ out)
{
    extern __shared__ __align__(1024) char sm[];
    const uint32_t sb = smem_u32(sm);
    const int tid = threadIdx.x, wid = tid >> 5, lane = tid & 31;
    const int mrow0 = (wid & 1) * 64;
    const int ncol0 = (wid >> 1) * 32;
    const int blk = blockIdx.x;

    // zero h1 ping-pong
    for (int i = tid; i < 32768 / 16; i += THREADS)
        ((uint4*)(sm + SM1_H1H0))[i] = make_uint4(0, 0, 0, 0);
    // weights fp16 (swizzled) + bias table (reordered)
    for (int idx = tid; idx < 256 * 64; idx += THREADS) {
        int g = idx >> 6, k = idx & 63;
        int n = (g & 63) * 4 + (g >> 6);
        int ba = n * 128 + (((k >> 3) ^ (n & 7)) << 4) + ((2 * k) & 15);
        *(__half*)(sm + SM1_WIH_H + ba) = __float2half_rn(Wih[idx]);
        *(__half*)(sm + SM1_WHH_H + ba) = __float2half_rn(Whh[idx]);
    }
    for (int g = tid; g < 256; g += THREADS) {
        int n = (g & 63) * 4 + (g >> 6);
        ((float*)(sm + SM1_BIAS))[n] = bih[g] + bhh[g];
    }
    __syncthreads();

    float cs[4][4];
#pragma unroll
    for (int a = 0; a < 4; a++)
#pragma unroll
        for (int b = 0; b < 4; b++) cs[a][b] = 0.f;

    // prefetch h0 for t=0 (1024 uint4, 2 per thread; layout linear in i)
    uint4 ph[2];
    {
        size_t base = ((size_t)0 * B + (size_t)blk * MT) * 8;
#pragma unroll
        for (int r = 0; r < 2; r++) ph[r] = g_h0[base + tid + r * THREADS];
    }

    for (int t = 0; t < T; t++) {
        const int rdH = (t & 1) ? SM1_H1H1 : SM1_H1H0;
        const int wrH = (t & 1) ? SM1_H1H0 : SM1_H1H1;

        // stage h0_t from prefetched regs into swizzled X tile (STS only)
#pragma unroll
        for (int r = 0; r < 2; r++) {
            int i = tid + r * THREADS;
            int row = i >> 3, ch = i & 7;
            uint32_t sa = row * 128 + ((ch ^ (row & 7)) << 4);
            *(uint4*)(sm + SM1_XH + sa) = ph[r];
        }

        float acc[4][4][4];
#pragma unroll
        for (int a = 0; a < 4; a++)
#pragma unroll
            for (int b = 0; b < 4; b++)
#pragma unroll
                for (int q = 0; q < 4; q++) acc[a][b][q] = 0.f;

        // H-GEMM first (h from prev epilogue; trailing sync of t-1 covers it)
        gemm_acc<4, 128, 128, true, true, 4>(sb + rdH, sb + SM1_WHH_H,
                                             acc, mrow0, ncol0, lane);
        __syncthreads();   // drains X stores (hidden behind H-GEMM)

        // prefetch next timestep (overlaps X-GEMM + epilogue)
        if (t + 1 < T) {
            size_t base = ((size_t)(t + 1) * B + (size_t)blk * MT) * 8;
#pragma unroll
            for (int r = 0; r < 2; r++) ph[r] = g_h0[base + tid + r * THREADS];
        }

        gemm_acc<4, 128, 128, true, true, 4>(sb + SM1_XH, sb + SM1_WIH_H,
                                             acc, mrow0, ncol0, lane);

        if (t < T - 1) {
            epilogue<false, 4>(acc, cs, sm, wrH,
                               (const float*)(sm + SM1_BIAS), 0,
                               mrow0, ncol0, lane);
        } else {
            // last step: write fp32 h into LN buffer (full precision for LayerNorm)
            epilogue<true, 4>(acc, cs, sm, 0,
                              (const float*)(sm + SM1_BIAS), SM1_LN,
                              mrow0, ncol0, lane);
        }
        __syncthreads();
    }

    // LayerNorm over final h1 (fp32 buffer), one thread per sample
    if (tid < MT) {
        const float* row = (const float*)(sm + SM1_LN) + tid * 68;
        float s = 0.f;
#pragma unroll
        for (int k = 0; k < 64; k++) s += row[k];
        float mean = s * (1.f / 64.f);
        float vs = 0.f;
#pragma unroll
        for (int k = 0; k < 64; k++) { float d = row[k] - mean; vs += d * d; }
        float rstd = rsqrtf(vs * (1.f / 64.f) + 1e-5f);
        float4* op = (float4*)(out + (size_t)(blk * MT + tid) * 64);
#pragma unroll
        for (int k = 0; k < 64; k += 4) {
            float4 o;
            o.x = (row[k + 0] - mean) * rstd * gamma[k + 0] + beta[k + 0];
            o.y = (row[k + 1] - mean) * rstd * gamma[k + 1] + beta[k + 1];
            o.z = (row[k + 2] - mean) * rstd * gamma[k + 2] + beta[k + 2];
            o.w = (row[k + 3] - mean) * rstd * gamma[k + 3] + beta[k + 3];
            op[k >> 2] = o;
        }
    }
}

// =====================================================================
extern "C" void kernel_launch(void* const* d_in, const int* in_sizes, int n_in,
                              void* d_out, int out_size) {
    (void)in_sizes; (void)n_in; (void)out_size;
    const float* x     = (const float*)d_in[0];
    const float* Wih0  = (const float*)d_in[1];
    const float* Whh0  = (const float*)d_in[2];
    const float* bih0  = (const float*)d_in[3];
    const float* bhh0  = (const float*)d_in[4];
    const float* Wih1  = (const float*)d_in[5];
    const float* Whh1  = (const float*)d_in[6];
    const float* bih1  = (const float*)d_in[7];
    const float* bhh1  = (const float*)d_in[8];
    const float* gamma = (const float*)d_in[9];
    const float* beta  = (const float*)d_in[10];
    float* out = (float*)d_out;

    cudaFuncSetAttribute(k_layer0, cudaFuncAttributeMaxDynamicSharedMemorySize, SM0_TOTAL);
    cudaFuncSetAttribute(k_layer1, cudaFuncAttributeMaxDynamicSharedMemorySize, SM1_TOTAL);

    k_layer0<<<B / MT, THREADS, SM0_TOTAL>>>(x, Wih0, Whh0, bih0, bhh0);
    k_layer1<<<B / MT, THREADS, SM1_TOTAL>>>(Wih1, Whh1, bih1, bhh1, gamma, beta, out);
}

// round 13
// speedup vs baseline: 3.8026x; 1.3578x over previous
#include <cuda_runtime.h>
#include <cuda_fp16.h>
#include <cstdint>
#include <cstddef>

constexpr int B  = 65536;
constexpr int T  = 30;
constexpr int MT = 128;          // samples per CTA
constexpr int THREADS = 512;     // 16 warps: 2 (m) x 8 (n), warp tile 64x32

// ---------------- Kernel0 smem offsets (bytes) ----------------
constexpr int SM0_X0    = 0;       // x ping [128][48B] K=16 (cols0-8, rest 0)
constexpr int SM0_X1    = 6144;    // x pong
constexpr int SM0_WIH   = 12288;   // [256 n][48B] Wih fp16 (cols0-8, rest 0)
constexpr int SM0_BIAS  = 24576;   // 256 f32, reordered gate cols
constexpr int SM0_HH0   = 25600;   // h0 fp16 ping [128][128B] swz
constexpr int SM0_HH1   = 41984;   // h0 fp16 pong
constexpr int SM0_WHH   = 58368;   // [256][128B] swz
constexpr int SM0_TOTAL = 91136;

// ---------------- Kernel1 smem offsets ----------------
constexpr int SM1_X0    = 0;       // staged h0 ping [128][128B] swz
constexpr int SM1_X1    = 16384;   // staged h0 pong
constexpr int SM1_H1H0  = 32768;   // h1 fp16 ping
constexpr int SM1_H1H1  = 49152;   // h1 fp16 pong
constexpr int SM1_WIH   = 65536;   // [256][128B] swz
constexpr int SM1_WHH   = 98304;
constexpr int SM1_BIAS  = 131072;  // 256 f32, reordered gate cols
constexpr int SM1_LN    = 132096;  // [128][68] f32 final h for LayerNorm
constexpr int SM1_TOTAL = 132096 + 128 * 68 * 4;   // 166912

// scratch: layer0 h fp16, [t][sample][8 x 16B chunks], coalesced both ways
__device__ uint4 g_h0[(size_t)T * B * 8];

// ---------------- helpers ----------------
__device__ __forceinline__ uint32_t smem_u32(const void* p) {
    uint32_t a;
    asm("{ .reg .u64 t; cvta.to.shared.u64 t, %1; cvt.u32.u64 %0, t; }"
        : "=r"(a) : "l"(p));
    return a;
}
// hardware tanh (sm_75+): 1 MUFU op, ~2^-11 accuracy
__device__ __forceinline__ float tanha(float x) {
    float r;
    asm("tanh.approx.f32 %0, %1;" : "=f"(r) : "f"(x));
    return r;
}
__device__ __forceinline__ float sigf(float x) {
    return fmaf(tanha(0.5f * x), 0.5f, 0.5f);
}
__device__ __forceinline__ uint32_t f2h2(float a, float b) {
    __half2 h = __floats2half2_rn(a, b);
    return *reinterpret_cast<uint32_t*>(&h);
}

__device__ __forceinline__ void ldsm4(uint32_t (&r)[4], uint32_t addr) {
    asm volatile("ldmatrix.sync.aligned.m8n8.x4.shared.b16 {%0,%1,%2,%3}, [%4];"
        : "=r"(r[0]), "=r"(r[1]), "=r"(r[2]), "=r"(r[3]) : "r"(addr));
}
__device__ __forceinline__ void mma_f16(float (&d)[4], const uint32_t (&a)[4],
                                        uint32_t b0, uint32_t b1) {
    asm volatile(
        "mma.sync.aligned.m16n8k16.row.col.f32.f16.f16.f32 "
        "{%0,%1,%2,%3},{%4,%5,%6,%7},{%8,%9},{%0,%1,%2,%3};"
        : "+f"(d[0]), "+f"(d[1]), "+f"(d[2]), "+f"(d[3])
        : "r"(a[0]), "r"(a[1]), "r"(a[2]), "r"(a[3]), "r"(b0), "r"(b1));
}

// Warp GEMM: A tile (MI*16 rows) x one B tile (32 n-cols), acc[MI][4][4].
// KS k16-steps; strides in bytes; SW = XOR-16B-chunk swizzle for 128B-stride tiles.
template<int KS, int SA, int SB, bool SWA, bool SWB, int MI>
__device__ __forceinline__ void gemm_acc(uint32_t aBase, uint32_t bBase,
                                         float (&acc)[MI][4][4],
                                         int mrow0, int ncol0, int lane)
{
    const int grp = lane >> 3, j = lane & 7;
    const int arow_off = ((grp & 1) << 3) + j;
    const int ach_off  = grp >> 1;
    const int brow_off = ((grp >> 1) << 3) + j;
    const int bch_off  = grp & 1;
#pragma unroll
    for (int kk = 0; kk < KS; kk++) {
        uint32_t a[MI][4];
#pragma unroll
        for (int mi = 0; mi < MI; mi++) {
            int row = mrow0 + mi * 16 + arow_off;
            int ch  = 2 * kk + ach_off;
            uint32_t ad = aBase + row * SA + ((SWA ? (ch ^ (row & 7)) : ch) << 4);
            ldsm4(a[mi], ad);
        }
#pragma unroll
        for (int ni = 0; ni < 2; ni++) {
            int row = ncol0 + ni * 16 + brow_off;
            int ch  = 2 * kk + bch_off;
            uint32_t bd = bBase + row * SB + ((SWB ? (ch ^ (row & 7)) : ch) << 4);
            uint32_t bf[4];
            ldsm4(bf, bd);
#pragma unroll
            for (int mi = 0; mi < MI; mi++) {
                mma_f16(acc[mi][2 * ni],     a[mi], bf[0], bf[1]);
                mma_f16(acc[mi][2 * ni + 1], a[mi], bf[2], bf[3]);
            }
        }
    }
}

// Gate epilogue: acc (pre-activations, cols = unit*4+type) + fp32 bias ->
// cell update -> h written fp16 into DESTINATION ping-pong tile (disjoint from
// GEMM sources, so no barrier before it), or fp32 into LN buffer on last step.
template<bool LNOUT, int MI>
__device__ __forceinline__ void epilogue(float (&acc)[MI][4][4], float (&cs)[MI][4],
                                         char* sm, int hhOff, const float* bias,
                                         int lnOff, int mrow0, int ncol0, int lane)
{
    const int  odd   = lane & 1;
    const int  rb    = mrow0 + (lane >> 2) + (odd ? 8 : 0);
    const int  ub    = (ncol0 >> 2) + ((lane & 3) >> 1);
#pragma unroll
    for (int mi = 0; mi < MI; mi++) {
#pragma unroll
        for (int nj = 0; nj < 4; nj++) {
            int n0 = ncol0 + nj * 8 + 2 * (lane & 3);
            float b0 = bias[n0], b1 = bias[n0 + 1];
            float c0 = acc[mi][nj][0] + b0, c1 = acc[mi][nj][1] + b1;
            float c2 = acc[mi][nj][2] + b0, c3 = acc[mi][nj][3] + b1;
            // even lanes hold (i,f) cols; odd lanes hold (g,o) cols; rows {r, r+8}
            float A0, A1, A2, A3;
            if (!odd) { A0 = sigf(c0);  A1 = sigf(c1); A2 = sigf(c2);  A3 = sigf(c3); }
            else      { A0 = tanha(c0); A1 = sigf(c1); A2 = tanha(c2); A3 = sigf(c3); }
            // exchange: even keeps row r (needs g,o from odd); odd keeps row r+8 (needs i,f)
            float v0 = odd ? A0 : A2;
            float v1 = odd ? A1 : A3;
            float r0 = __shfl_xor_sync(0xffffffffu, v0, 1);
            float r1 = __shfl_xor_sync(0xffffffffu, v1, 1);
            float iv = odd ? r0 : A0;
            float fv = odd ? r1 : A1;
            float gv = odd ? A2 : r0;
            float ov = odd ? A3 : r1;
            float cc = fv * cs[mi][nj] + iv * gv;
            cs[mi][nj] = cc;
            float hv = ov * tanha(cc);
            int row = rb + mi * 16;
            int u   = ub + 2 * nj;
            if (LNOUT) {
                ((float*)(sm + lnOff))[row * 68 + u] = hv;
            } else {
                __half hh = __float2half_rn(hv);
                int ch = u >> 3;
                int ba = row * 128 + ((ch ^ (row & 7)) << 4) + ((2 * u) & 15);
                *(__half*)(sm + hhOff + ba) = hh;
            }
        }
    }
}

// =====================================================================
// Kernel 0: x -> h0 (fp16) -> global scratch
// =====================================================================
__global__ void __launch_bounds__(THREADS, 1) k_layer0(
    const float* __restrict__ x,
    const float* __restrict__ Wih, const float* __restrict__ Whh,
    const float* __restrict__ bih, const float* __restrict__ bhh)
{
    extern __shared__ __align__(1024) char sm[];
    const uint32_t sb = smem_u32(sm);
    const int tid = threadIdx.x, wid = tid >> 5, lane = tid & 31;
    const int mrow0 = (wid & 1) * 64;
    const int ncol0 = (wid >> 1) * 32;
    const int blk = blockIdx.x;

    // prefetch x_0 early (overlaps weight staging)
    float xv[9];
    if (tid < MT) {
        const float* xr = x + ((size_t)(blk * MT + tid) * T + 0) * 9;
#pragma unroll
        for (int i = 0; i < 9; i++) xv[i] = xr[i];
    }

    // zero h ping-pong + X/WIH regions
    for (int i = tid; i < 32768 / 16; i += THREADS)
        ((uint4*)(sm + SM0_HH0))[i] = make_uint4(0, 0, 0, 0);
    for (int i = tid; i < 24576 / 16; i += THREADS)
        ((uint4*)(sm + SM0_X0))[i] = make_uint4(0, 0, 0, 0);
    __syncthreads();

    // Wih0 fp16 [256 n][48B]: cols 0-8 weights, rest zero; bias fp32 table
    for (int idx = tid; idx < 256 * 9; idx += THREADS) {
        int g = idx / 9, i2 = idx - g * 9;
        int n = (g & 63) * 4 + (g >> 6);
        *(__half*)(sm + SM0_WIH + n * 48 + 2 * i2) = __float2half_rn(Wih[idx]);
    }
    for (int g = tid; g < 256; g += THREADS) {
        int n = (g & 63) * 4 + (g >> 6);
        ((float*)(sm + SM0_BIAS))[n] = bih[g] + bhh[g];
    }
    // Whh0 fp16 tile (swizzled)
    for (int idx = tid; idx < 256 * 64; idx += THREADS) {
        int g = idx >> 6, k = idx & 63;
        int n = (g & 63) * 4 + (g >> 6);
        int ba = n * 128 + (((k >> 3) ^ (n & 7)) << 4) + ((2 * k) & 15);
        *(__half*)(sm + SM0_WHH + ba) = __float2half_rn(Whh[idx]);
    }
    // stage x_0 into X0
    if (tid < MT) {
        char* rp = sm + SM0_X0 + tid * 48;
        ((uint4*)rp)[0] = make_uint4(f2h2(xv[0], xv[1]), f2h2(xv[2], xv[3]),
                                     f2h2(xv[4], xv[5]), f2h2(xv[6], xv[7]));
        ((uint4*)rp)[1] = make_uint4(f2h2(xv[8], 0.f), 0, 0, 0);
    }
    __syncthreads();

    float cs[4][4];
#pragma unroll
    for (int a = 0; a < 4; a++)
#pragma unroll
        for (int b = 0; b < 4; b++) cs[a][b] = 0.f;

    for (int t = 0; t < T; t++) {
        const int rdH = (t & 1) ? SM0_HH1 : SM0_HH0;
        const int wrH = (t & 1) ? SM0_HH0 : SM0_HH1;
        const int rdX = (t & 1) ? SM0_X1 : SM0_X0;
        const int wrX = (t & 1) ? SM0_X0 : SM0_X1;

        // prefetch x_{t+1} (LDG issued at top; lands before staging below)
        if (t + 1 < T && tid < MT) {
            const float* xr = x + ((size_t)(blk * MT + tid) * T + (t + 1)) * 9;
#pragma unroll
            for (int i = 0; i < 9; i++) xv[i] = xr[i];
        }

        // store h_{t-1} -> global scratch (reads rdH: read/read vs H-GEMM)
        if (t > 0) {
            for (int i = tid; i < 1024; i += THREADS) {
                int row = i >> 3, ch = i & 7;
                uint32_t sa = row * 128 + ((ch ^ (row & 7)) << 4);
                size_t gi = ((size_t)(t - 1) * B + (size_t)blk * MT + row) * 8 + ch;
                g_h0[gi] = *(uint4*)(sm + rdH + sa);
            }
        }

        float acc[4][4][4];
#pragma unroll
        for (int a = 0; a < 4; a++)
#pragma unroll
            for (int b = 0; b < 4; b++)
#pragma unroll
                for (int q = 0; q < 4; q++) acc[a][b][q] = 0.f;

        gemm_acc<4, 128, 128, true, true, 4>(sb + rdH, sb + SM0_WHH,
                                             acc, mrow0, ncol0, lane);
        gemm_acc<1, 48, 48, false, false, 4>(sb + rdX, sb + SM0_WIH,
                                             acc, mrow0, ncol0, lane);

        // stage x_{t+1} into pong (disjoint from rdX) — no barrier needed
        if (t + 1 < T && tid < MT) {
            char* rp = sm + wrX + tid * 48;
            ((uint4*)rp)[0] = make_uint4(f2h2(xv[0], xv[1]), f2h2(xv[2], xv[3]),
                                         f2h2(xv[4], xv[5]), f2h2(xv[6], xv[7]));
            ((uint4*)rp)[1] = make_uint4(f2h2(xv[8], 0.f), 0, 0, 0);
        }

        // epilogue writes wrH (disjoint from rdH/rdX) — no barrier before it
        epilogue<false, 4>(acc, cs, sm, wrH, (const float*)(sm + SM0_BIAS),
                           0, mrow0, ncol0, lane);
        __syncthreads();   // single barrier per timestep
    }

    // store final h_{T-1} (lives in buf[T&1] = buf0)
    {
        const int rdH = (T & 1) ? SM0_HH1 : SM0_HH0;
        for (int i = tid; i < 1024; i += THREADS) {
            int row = i >> 3, ch = i & 7;
            uint32_t sa = row * 128 + ((ch ^ (row & 7)) << 4);
            size_t gi = ((size_t)(T - 1) * B + (size_t)blk * MT + row) * 8 + ch;
            g_h0[gi] = *(uint4*)(sm + rdH + sa);
        }
    }
}

// =====================================================================
// Kernel 1: h0 -> LSTM -> LayerNorm(h_T) -> out
// =====================================================================
__global__ void __launch_bounds__(THREADS, 1) k_layer1(
    const float* __restrict__ Wih, const float* __restrict__ Whh,
    const float* __restrict__ bih, const float* __restrict__ bhh,
    const float* __restrict__ gamma, const float* __restrict__ beta,
    float* __restrict__ out)
{
    extern __shared__ __align__(1024) char sm[];
    const uint32_t sb = smem_u32(sm);
    const int tid = threadIdx.x, wid = tid >> 5, lane = tid & 31;
    const int mrow0 = (wid & 1) * 64;
    const int ncol0 = (wid >> 1) * 32;
    const int blk = blockIdx.x;

    // prefetch h0_0 early (overlaps weight staging)
    uint4 ph[2];
    {
        size_t base = ((size_t)0 * B + (size_t)blk * MT) * 8;
#pragma unroll
        for (int r = 0; r < 2; r++) ph[r] = g_h0[base + tid + r * THREADS];
    }

    // zero h1 ping-pong
    for (int i = tid; i < 32768 / 16; i += THREADS)
        ((uint4*)(sm + SM1_H1H0))[i] = make_uint4(0, 0, 0, 0);
    // weights fp16 (swizzled) + bias table (reordered)
    for (int idx = tid; idx < 256 * 64; idx += THREADS) {
        int g = idx >> 6, k = idx & 63;
        int n = (g & 63) * 4 + (g >> 6);
        int ba = n * 128 + (((k >> 3) ^ (n & 7)) << 4) + ((2 * k) & 15);
        *(__half*)(sm + SM1_WIH + ba) = __float2half_rn(Wih[idx]);
        *(__half*)(sm + SM1_WHH + ba) = __float2half_rn(Whh[idx]);
    }
    for (int g = tid; g < 256; g += THREADS) {
        int n = (g & 63) * 4 + (g >> 6);
        ((float*)(sm + SM1_BIAS))[n] = bih[g] + bhh[g];
    }
    // stage h0_0 into X0
#pragma unroll
    for (int r = 0; r < 2; r++) {
        int i = tid + r * THREADS;
        int row = i >> 3, ch = i & 7;
        uint32_t sa = row * 128 + ((ch ^ (row & 7)) << 4);
        *(uint4*)(sm + SM1_X0 + sa) = ph[r];
    }
    __syncthreads();

    float cs[4][4];
#pragma unroll
    for (int a = 0; a < 4; a++)
#pragma unroll
        for (int b = 0; b < 4; b++) cs[a][b] = 0.f;

    for (int t = 0; t < T; t++) {
        const int rdH = (t & 1) ? SM1_H1H1 : SM1_H1H0;
        const int wrH = (t & 1) ? SM1_H1H0 : SM1_H1H1;
        const int rdX = (t & 1) ? SM1_X1 : SM1_X0;
        const int wrX = (t & 1) ? SM1_X0 : SM1_X1;

        // prefetch h0_{t+1} (LDG at top; lands before staging below)
        if (t + 1 < T) {
            size_t base = ((size_t)(t + 1) * B + (size_t)blk * MT) * 8;
#pragma unroll
            for (int r = 0; r < 2; r++) ph[r] = g_h0[base + tid + r * THREADS];
        }

        float acc[4][4][4];
#pragma unroll
        for (int a = 0; a < 4; a++)
#pragma unroll
            for (int b = 0; b < 4; b++)
#pragma unroll
                for (int q = 0; q < 4; q++) acc[a][b][q] = 0.f;

        gemm_acc<4, 128, 128, true, true, 4>(sb + rdH, sb + SM1_WHH,
                                             acc, mrow0, ncol0, lane);
        gemm_acc<4, 128, 128, true, true, 4>(sb + rdX, sb + SM1_WIH,
                                             acc, mrow0, ncol0, lane);

        // stage h0_{t+1} into pong (disjoint from rdX) — no barrier needed
        if (t + 1 < T) {
#pragma unroll
            for (int r = 0; r < 2; r++) {
                int i = tid + r * THREADS;
                int row = i >> 3, ch = i & 7;
                uint32_t sa = row * 128 + ((ch ^ (row & 7)) << 4);
                *(uint4*)(sm + wrX + sa) = ph[r];
            }
        }

        if (t < T - 1) {
            epilogue<false, 4>(acc, cs, sm, wrH,
                               (const float*)(sm + SM1_BIAS), 0,
                               mrow0, ncol0, lane);
        } else {
            // last step: write fp32 h into LN buffer (full precision for LayerNorm)
            epilogue<true, 4>(acc, cs, sm, 0,
                              (const float*)(sm + SM1_BIAS), SM1_LN,
                              mrow0, ncol0, lane);
        }
        __syncthreads();   // single barrier per timestep
    }

    // LayerNorm over final h1 (fp32 buffer), one thread per sample
    if (tid < MT) {
        const float* row = (const float*)(sm + SM1_LN) + tid * 68;
        float s = 0.f;
#pragma unroll
        for (int k = 0; k < 64; k++) s += row[k];
        float mean = s * (1.f / 64.f);
        float vs = 0.f;
#pragma unroll
        for (int k = 0; k < 64; k++) { float d = row[k] - mean; vs += d * d; }
        float rstd = rsqrtf(vs * (1.f / 64.f) + 1e-5f);
        float4* op = (float4*)(out + (size_t)(blk * MT + tid) * 64);
#pragma unroll
        for (int k = 0; k < 64; k += 4) {
            float4 o;
            o.x = (row[k + 0] - mean) * rstd * gamma[k + 0] + beta[k + 0];
            o.y = (row[k + 1] - mean) * rstd * gamma[k + 1] + beta[k + 1];
            o.z = (row[k + 2] - mean) * rstd * gamma[k + 2] + beta[k + 2];
            o.w = (row[k + 3] - mean) * rstd * gamma[k + 3] + beta[k + 3];
            op[k >> 2] = o;
        }
    }
}

// =====================================================================
extern "C" void kernel_launch(void* const* d_in, const int* in_sizes, int n_in,
                              void* d_out, int out_size) {
    (void)in_sizes; (void)n_in; (void)out_size;
    const float* x     = (const float*)d_in[0];
    const float* Wih0  = (const float*)d_in[1];
    const float* Whh0  = (const float*)d_in[2];
    const float* bih0  = (const float*)d_in[3];
    const float* bhh0  = (const float*)d_in[4];
    const float* Wih1  = (const float*)d_in[5];
    const float* Whh1  = (const float*)d_in[6];
    const float* bih1  = (const float*)d_in[7];
    const float* bhh1  = (const float*)d_in[8];
    const float* gamma = (const float*)d_in[9];
    const float* beta  = (const float*)d_in[10];
    float* out = (float*)d_out;

    cudaFuncSetAttribute(k_layer0, cudaFuncAttributeMaxDynamicSharedMemorySize, SM0_TOTAL);
    cudaFuncSetAttribute(k_layer1, cudaFuncAttributeMaxDynamicSharedMemorySize, SM1_TOTAL);

    k_layer0<<<B / MT, THREADS, SM0_TOTAL>>>(x, Wih0, Whh0, bih0, bhh0);
    k_layer1<<<B / MT, THREADS, SM1_TOTAL>>>(Wih1, Whh1, bih1, bhh1, gamma, beta, out);
}

// round 14
// speedup vs baseline: 3.8083x; 1.0015x over previous
#include <cuda_runtime.h>
#include <cuda_fp16.h>
#include <cstdint>
#include <cstddef>

constexpr int B  = 65536;
constexpr int T  = 30;
constexpr int MT = 128;          // samples per CTA
constexpr int THREADS = 512;     // 16 warps: 2 (m) x 8 (n), warp tile 64x32

// ---------------- Kernel0 smem offsets (bytes) ----------------
constexpr int SM0_X0    = 0;       // x ping [128][48B] K=16 (cols0-8, rest 0)
constexpr int SM0_X1    = 6144;    // x pong
constexpr int SM0_WIH   = 12288;   // [256 n][48B] Wih fp16 (cols0-8, rest 0)
constexpr int SM0_BIAS  = 24576;   // 256 f32, reordered gate cols
constexpr int SM0_HH0   = 25600;   // h0 fp16 ping [128][128B] swz
constexpr int SM0_HH1   = 41984;   // h0 fp16 pong
constexpr int SM0_WHH   = 58368;   // [256][128B] swz
constexpr int SM0_TOTAL = 91136;

// ---------------- Kernel1 smem offsets ----------------
constexpr int SM1_X0    = 0;       // staged h0 ping [128][128B] swz
constexpr int SM1_X1    = 16384;   // staged h0 pong
constexpr int SM1_H1H0  = 32768;   // h1 fp16 ping
constexpr int SM1_H1H1  = 49152;   // h1 fp16 pong
constexpr int SM1_WIH   = 65536;   // [256][128B] swz
constexpr int SM1_WHH   = 98304;
constexpr int SM1_BIAS  = 131072;  // 256 f32, reordered gate cols
constexpr int SM1_LN    = 132096;  // [128][68] f32 final h for LayerNorm
constexpr int SM1_TOTAL = 132096 + 128 * 68 * 4;   // 166912

// scratch: layer0 h fp16, [t][sample][8 x 16B chunks], coalesced both ways
__device__ uint4 g_h0[(size_t)T * B * 8];

// ---------------- helpers ----------------
__device__ __forceinline__ uint32_t smem_u32(const void* p) {
    uint32_t a;
    asm("{ .reg .u64 t; cvta.to.shared.u64 t, %1; cvt.u32.u64 %0, t; }"
        : "=r"(a) : "l"(p));
    return a;
}
// hardware tanh (sm_75+): 1 MUFU op, ~2^-11 accuracy
__device__ __forceinline__ float tanha(float x) {
    float r;
    asm("tanh.approx.f32 %0, %1;" : "=f"(r) : "f"(x));
    return r;
}
__device__ __forceinline__ float sigf(float x) {
    return fmaf(tanha(0.5f * x), 0.5f, 0.5f);
}
__device__ __forceinline__ uint32_t f2h2(float a, float b) {
    __half2 h = __floats2half2_rn(a, b);
    return *reinterpret_cast<uint32_t*>(&h);
}

__device__ __forceinline__ void ldsm4(uint32_t (&r)[4], uint32_t addr) {
    asm volatile("ldmatrix.sync.aligned.m8n8.x4.shared.b16 {%0,%1,%2,%3}, [%4];"
        : "=r"(r[0]), "=r"(r[1]), "=r"(r[2]), "=r"(r[3]) : "r"(addr));
}
__device__ __forceinline__ void mma_f16(float (&d)[4], const uint32_t (&a)[4],
                                        uint32_t b0, uint32_t b1) {
    asm volatile(
        "mma.sync.aligned.m16n8k16.row.col.f32.f16.f16.f32 "
        "{%0,%1,%2,%3},{%4,%5,%6,%7},{%8,%9},{%0,%1,%2,%3};"
        : "+f"(d[0]), "+f"(d[1]), "+f"(d[2]), "+f"(d[3])
        : "r"(a[0]), "r"(a[1]), "r"(a[2]), "r"(a[3]), "r"(b0), "r"(b1));
}

// Warp GEMM: A tile (MI*16 rows) x one B tile (32 n-cols), acc[MI][4][4].
// KS k16-steps; strides in bytes; SW = XOR-16B-chunk swizzle for 128B-stride tiles.
template<int KS, int SA, int SB, bool SWA, bool SWB, int MI>
__device__ __forceinline__ void gemm_acc(uint32_t aBase, uint32_t bBase,
                                         float (&acc)[MI][4][4],
                                         int mrow0, int ncol0, int lane)
{
    const int grp = lane >> 3, j = lane & 7;
    const int arow_off = ((grp & 1) << 3) + j;
    const int ach_off  = grp >> 1;
    const int brow_off = ((grp >> 1) << 3) + j;
    const int bch_off  = grp & 1;
#pragma unroll
    for (int kk = 0; kk < KS; kk++) {
        uint32_t a[MI][4];
#pragma unroll
        for (int mi = 0; mi < MI; mi++) {
            int row = mrow0 + mi * 16 + arow_off;
            int ch  = 2 * kk + ach_off;
            uint32_t ad = aBase + row * SA + ((SWA ? (ch ^ (row & 7)) : ch) << 4);
            ldsm4(a[mi], ad);
        }
#pragma unroll
        for (int ni = 0; ni < 2; ni++) {
            int row = ncol0 + ni * 16 + brow_off;
            int ch  = 2 * kk + bch_off;
            uint32_t bd = bBase + row * SB + ((SWB ? (ch ^ (row & 7)) : ch) << 4);
            uint32_t bf[4];
            ldsm4(bf, bd);
#pragma unroll
            for (int mi = 0; mi < MI; mi++) {
                mma_f16(acc[mi][2 * ni],     a[mi], bf[0], bf[1]);
                mma_f16(acc[mi][2 * ni + 1], a[mi], bf[2], bf[3]);
            }
        }
    }
}

// Gate epilogue: acc (pre-activations, cols = unit*4+type) + fp32 bias ->
// cell update -> h written fp16 into DESTINATION ping-pong tile (disjoint from
// GEMM sources, so no barrier before it), or fp32 into LN buffer on last step.
template<bool LNOUT, int MI>
__device__ __forceinline__ void epilogue(float (&acc)[MI][4][4], float (&cs)[MI][4],
                                         char* sm, int hhOff, const float* bias,
                                         int lnOff, int mrow0, int ncol0, int lane)
{
    const int  odd   = lane & 1;
    const int  rb    = mrow0 + (lane >> 2) + (odd ? 8 : 0);
    const int  ub    = (ncol0 >> 2) + ((lane & 3) >> 1);
#pragma unroll
    for (int mi = 0; mi < MI; mi++) {
#pragma unroll
        for (int nj = 0; nj < 4; nj++) {
            int n0 = ncol0 + nj * 8 + 2 * (lane & 3);
            float b0 = bias[n0], b1 = bias[n0 + 1];
            float c0 = acc[mi][nj][0] + b0, c1 = acc[mi][nj][1] + b1;
            float c2 = acc[mi][nj][2] + b0, c3 = acc[mi][nj][3] + b1;
            // even lanes hold (i,f) cols; odd lanes hold (g,o) cols; rows {r, r+8}
            float A0, A1, A2, A3;
            if (!odd) { A0 = sigf(c0);  A1 = sigf(c1); A2 = sigf(c2);  A3 = sigf(c3); }
            else      { A0 = tanha(c0); A1 = sigf(c1); A2 = tanha(c2); A3 = sigf(c3); }
            // exchange: even keeps row r (needs g,o from odd); odd keeps row r+8 (needs i,f)
            float v0 = odd ? A0 : A2;
            float v1 = odd ? A1 : A3;
            float r0 = __shfl_xor_sync(0xffffffffu, v0, 1);
            float r1 = __shfl_xor_sync(0xffffffffu, v1, 1);
            float iv = odd ? r0 : A0;
            float fv = odd ? r1 : A1;
            float gv = odd ? A2 : r0;
            float ov = odd ? A3 : r1;
            float cc = fv * cs[mi][nj] + iv * gv;
            cs[mi][nj] = cc;
            float hv = ov * tanha(cc);
            int row = rb + mi * 16;
            int u   = ub + 2 * nj;
            if (LNOUT) {
                ((float*)(sm + lnOff))[row * 68 + u] = hv;
            } else {
                __half hh = __float2half_rn(hv);
                int ch = u >> 3;
                int ba = row * 128 + ((ch ^ (row & 7)) << 4) + ((2 * u) & 15);
                *(__half*)(sm + hhOff + ba) = hh;
            }
        }
    }
}

// =====================================================================
// Kernel 0: x -> h0 (fp16) -> global scratch
// =====================================================================
__global__ void __launch_bounds__(THREADS, 1) k_layer0(
    const float* __restrict__ x,
    const float* __restrict__ Wih, const float* __restrict__ Whh,
    const float* __restrict__ bih, const float* __restrict__ bhh)
{
    extern __shared__ __align__(1024) char sm[];
    const uint32_t sb = smem_u32(sm);
    const int tid = threadIdx.x, wid = tid >> 5, lane = tid & 31;
    const int mrow0 = (wid & 1) * 64;
    const int ncol0 = (wid >> 1) * 32;
    const int blk = blockIdx.x;

    // prefetch x_0 early (overlaps weight staging)
    float xv[9];
    if (tid < MT) {
        const float* xr = x + ((size_t)(blk * MT + tid) * T + 0) * 9;
#pragma unroll
        for (int i = 0; i < 9; i++) xv[i] = xr[i];
    }

    // zero h ping-pong + X/WIH regions
    for (int i = tid; i < 32768 / 16; i += THREADS)
        ((uint4*)(sm + SM0_HH0))[i] = make_uint4(0, 0, 0, 0);
    for (int i = tid; i < 24576 / 16; i += THREADS)
        ((uint4*)(sm + SM0_X0))[i] = make_uint4(0, 0, 0, 0);
    __syncthreads();

    // Wih0 fp16 [256 n][48B]: cols 0-8 weights, rest zero; bias fp32 table
    for (int idx = tid; idx < 256 * 9; idx += THREADS) {
        int g = idx / 9, i2 = idx - g * 9;
        int n = (g & 63) * 4 + (g >> 6);
        *(__half*)(sm + SM0_WIH + n * 48 + 2 * i2) = __float2half_rn(Wih[idx]);
    }
    for (int g = tid; g < 256; g += THREADS) {
        int n = (g & 63) * 4 + (g >> 6);
        ((float*)(sm + SM0_BIAS))[n] = bih[g] + bhh[g];
    }
    // Whh0 fp16 tile (swizzled)
    for (int idx = tid; idx < 256 * 64; idx += THREADS) {
        int g = idx >> 6, k = idx & 63;
        int n = (g & 63) * 4 + (g >> 6);
        int ba = n * 128 + (((k >> 3) ^ (n & 7)) << 4) + ((2 * k) & 15);
        *(__half*)(sm + SM0_WHH + ba) = __float2half_rn(Whh[idx]);
    }
    // stage x_0 into X0
    if (tid < MT) {
        char* rp = sm + SM0_X0 + tid * 48;
        ((uint4*)rp)[0] = make_uint4(f2h2(xv[0], xv[1]), f2h2(xv[2], xv[3]),
                                     f2h2(xv[4], xv[5]), f2h2(xv[6], xv[7]));
        ((uint4*)rp)[1] = make_uint4(f2h2(xv[8], 0.f), 0, 0, 0);
    }
    __syncthreads();

    float cs[4][4];
#pragma unroll
    for (int a = 0; a < 4; a++)
#pragma unroll
        for (int b = 0; b < 4; b++) cs[a][b] = 0.f;

    for (int t = 0; t < T; t++) {
        const int rdH = (t & 1) ? SM0_HH1 : SM0_HH0;
        const int wrH = (t & 1) ? SM0_HH0 : SM0_HH1;
        const int rdX = (t & 1) ? SM0_X1 : SM0_X0;
        const int wrX = (t & 1) ? SM0_X0 : SM0_X1;

        // prefetch x_{t+1} (LDG issued at top; lands before staging below)
        if (t + 1 < T && tid < MT) {
            const float* xr = x + ((size_t)(blk * MT + tid) * T + (t + 1)) * 9;
#pragma unroll
            for (int i = 0; i < 9; i++) xv[i] = xr[i];
        }

        // store h_{t-1} -> global scratch (reads rdH: read/read vs H-GEMM)
        if (t > 0) {
            for (int i = tid; i < 1024; i += THREADS) {
                int row = i >> 3, ch = i & 7;
                uint32_t sa = row * 128 + ((ch ^ (row & 7)) << 4);
                size_t gi = ((size_t)(t - 1) * B + (size_t)blk * MT + row) * 8 + ch;
                g_h0[gi] = *(uint4*)(sm + rdH + sa);
            }
        }

        float acc[4][4][4];
#pragma unroll
        for (int a = 0; a < 4; a++)
#pragma unroll
            for (int b = 0; b < 4; b++)
#pragma unroll
                for (int q = 0; q < 4; q++) acc[a][b][q] = 0.f;

        gemm_acc<4, 128, 128, true, true, 4>(sb + rdH, sb + SM0_WHH,
                                             acc, mrow0, ncol0, lane);
        gemm_acc<1, 48, 48, false, false, 4>(sb + rdX, sb + SM0_WIH,
                                             acc, mrow0, ncol0, lane);

        // stage x_{t+1} into pong (disjoint from rdX) — no barrier needed
        if (t + 1 < T && tid < MT) {
            char* rp = sm + wrX + tid * 48;
            ((uint4*)rp)[0] = make_uint4(f2h2(xv[0], xv[1]), f2h2(xv[2], xv[3]),
                                         f2h2(xv[4], xv[5]), f2h2(xv[6], xv[7]));
            ((uint4*)rp)[1] = make_uint4(f2h2(xv[8], 0.f), 0, 0, 0);
        }

        // epilogue writes wrH (disjoint from rdH/rdX) — no barrier before it
        epilogue<false, 4>(acc, cs, sm, wrH, (const float*)(sm + SM0_BIAS),
                           0, mrow0, ncol0, lane);
        __syncthreads();   // single barrier per timestep
    }

    // store final h_{T-1} (lives in buf[T&1] = buf0)
    {
        const int rdH = (T & 1) ? SM0_HH1 : SM0_HH0;
        for (int i = tid; i < 1024; i += THREADS) {
            int row = i >> 3, ch = i & 7;
            uint32_t sa = row * 128 + ((ch ^ (row & 7)) << 4);
            size_t gi = ((size_t)(T - 1) * B + (size_t)blk * MT + row) * 8 + ch;
            g_h0[gi] = *(uint4*)(sm + rdH + sa);
        }
    }
}

// =====================================================================
// Kernel 1: h0 -> LSTM -> LayerNorm(h_T) -> out
// =====================================================================
__global__ void __launch_bounds__(THREADS, 1) k_layer1(
    const float* __restrict__ Wih, const float* __restrict__ Whh,
    const float* __restrict__ bih, const float* __restrict__ bhh,
    const float* __restrict__ gamma, const float* __restrict__ beta,
    float* __restrict__ out)
{
    extern __shared__ __align__(1024) char sm[];
    const uint32_t sb = smem_u32(sm);
    const int tid = threadIdx.x, wid = tid >> 5, lane = tid & 31;
    const int mrow0 = (wid & 1) * 64;
    const int ncol0 = (wid >> 1) * 32;
    const int blk = blockIdx.x;

    // prefetch h0_0 early (overlaps weight staging)
    uint4 ph[2];
    {
        size_t base = ((size_t)0 * B + (size_t)blk * MT) * 8;
#pragma unroll
        for (int r = 0; r < 2; r++) ph[r] = g_h0[base + tid + r * THREADS];
    }

    // zero h1 ping-pong
    for (int i = tid; i < 32768 / 16; i += THREADS)
        ((uint4*)(sm + SM1_H1H0))[i] = make_uint4(0, 0, 0, 0);
    // weights fp16 (swizzled) + bias table (reordered)
    for (int idx = tid; idx < 256 * 64; idx += THREADS) {
        int g = idx >> 6, k = idx & 63;
        int n = (g & 63) * 4 + (g >> 6);
        int ba = n * 128 + (((k >> 3) ^ (n & 7)) << 4) + ((2 * k) & 15);
        *(__half*)(sm + SM1_WIH + ba) = __float2half_rn(Wih[idx]);
        *(__half*)(sm + SM1_WHH + ba) = __float2half_rn(Whh[idx]);
    }
    for (int g = tid; g < 256; g += THREADS) {
        int n = (g & 63) * 4 + (g >> 6);
        ((float*)(sm + SM1_BIAS))[n] = bih[g] + bhh[g];
    }
    // stage h0_0 into X0
#pragma unroll
    for (int r = 0; r < 2; r++) {
        int i = tid + r * THREADS;
        int row = i >> 3, ch = i & 7;
        uint32_t sa = row * 128 + ((ch ^ (row & 7)) << 4);
        *(uint4*)(sm + SM1_X0 + sa) = ph[r];
    }
    __syncthreads();

    float cs[4][4];
#pragma unroll
    for (int a = 0; a < 4; a++)
#pragma unroll
        for (int b = 0; b < 4; b++) cs[a][b] = 0.f;

    for (int t = 0; t < T; t++) {
        const int rdH = (t & 1) ? SM1_H1H1 : SM1_H1H0;
        const int wrH = (t & 1) ? SM1_H1H0 : SM1_H1H1;
        const int rdX = (t & 1) ? SM1_X1 : SM1_X0;
        const int wrX = (t & 1) ? SM1_X0 : SM1_X1;

        // prefetch h0_{t+1} (LDG at top; lands before staging below)
        if (t + 1 < T) {
            size_t base = ((size_t)(t + 1) * B + (size_t)blk * MT) * 8;
#pragma unroll
            for (int r = 0; r < 2; r++) ph[r] = g_h0[base + tid + r * THREADS];
        }

        float acc[4][4][4];
#pragma unroll
        for (int a = 0; a < 4; a++)
#pragma unroll
            for (int b = 0; b < 4; b++)
#pragma unroll
                for (int q = 0; q < 4; q++) acc[a][b][q] = 0.f;

        gemm_acc<4, 128, 128, true, true, 4>(sb + rdH, sb + SM1_WHH,
                                             acc, mrow0, ncol0, lane);
        gemm_acc<4, 128, 128, true, true, 4>(sb + rdX, sb + SM1_WIH,
                                             acc, mrow0, ncol0, lane);

        // stage h0_{t+1} into pong (disjoint from rdX) — no barrier needed
        if (t + 1 < T) {
#pragma unroll
            for (int r = 0; r < 2; r++) {
                int i = tid + r * THREADS;
                int row = i >> 3, ch = i & 7;
                uint32_t sa = row * 128 + ((ch ^ (row & 7)) << 4);
                *(uint4*)(sm + wrX + sa) = ph[r];
            }
        }

        if (t < T - 1) {
            epilogue<false, 4>(acc, cs, sm, wrH,
                               (const float*)(sm + SM1_BIAS), 0,
                               mrow0, ncol0, lane);
        } else {
            // last step: write fp32 h into LN buffer (full precision for LayerNorm)
            epilogue<true, 4>(acc, cs, sm, 0,
                              (const float*)(sm + SM1_BIAS), SM1_LN,
                              mrow0, ncol0, lane);
        }
        __syncthreads();   // single barrier per timestep
    }

    // LayerNorm over final h1 (fp32 buffer), one thread per sample
    if (tid < MT) {
        const float* row = (const float*)(sm + SM1_LN) + tid * 68;
        float s = 0.f;
#pragma unroll
        for (int k = 0; k < 64; k++) s += row[k];
        float mean = s * (1.f / 64.f);
        float vs = 0.f;
#pragma unroll
        for (int k = 0; k < 64; k++) { float d = row[k] - mean; vs += d * d; }
        float rstd = rsqrtf(vs * (1.f / 64.f) + 1e-5f);
        float4* op = (float4*)(out + (size_t)(blk * MT + tid) * 64);
#pragma unroll
        for (int k = 0; k < 64; k += 4) {
            float4 o;
            o.x = (row[k + 0] - mean) * rstd * gamma[k + 0] + beta[k + 0];
            o.y = (row[k + 1] - mean) * rstd * gamma[k + 1] + beta[k + 1];
            o.z = (row[k + 2] - mean) * rstd * gamma[k + 2] + beta[k + 2];
            o.w = (row[k + 3] - mean) * rstd * gamma[k + 3] + beta[k + 3];
            op[k >> 2] = o;
        }
    }
}

// =====================================================================
extern "C" void kernel_launch(void* const* d_in, const int* in_sizes, int n_in,
                              void* d_out, int out_size) {
    (void)in_sizes; (void)n_in; (void)out_size;
    const float* x     = (const float*)d_in[0];
    const float* Wih0  = (const float*)d_in[1];
    const float* Whh0  = (const float*)d_in[2];
    const float* bih0  = (const float*)d_in[3];
    const float* bhh0  = (const float*)d_in[4];
    const float* Wih1  = (const float*)d_in[5];
    const float* Whh1  = (const float*)d_in[6];
    const float* bih1  = (const float*)d_in[7];
    const float* bhh1  = (const float*)d_in[8];
    const float* gamma = (const float*)d_in[9];
    const float* beta  = (const float*)d_in[10];
    float* out = (float*)d_out;

    cudaFuncSetAttribute(k_layer0, cudaFuncAttributeMaxDynamicSharedMemorySize, SM0_TOTAL);
    cudaFuncSetAttribute(k_layer1, cudaFuncAttributeMaxDynamicSharedMemorySize, SM1_TOTAL);

    k_layer0<<<B / MT, THREADS, SM0_TOTAL>>>(x, Wih0, Whh0, bih0, bhh0);
    k_layer1<<<B / MT, THREADS, SM1_TOTAL>>>(Wih1, Whh1, bih1, bhh1, gamma, beta, out);
}